// round 3
// baseline (speedup 1.0000x reference)
#include <cuda_runtime.h>
#include <math.h>

#define N_ENT 20000
#define DIM   200
#define RR    20
#define NB    20
#define NL    2
#define NT    2
#define NE    250000
#define NQ    8192
#define HID   256
#define D3    600

#define BM 128
#define EGRID 1973                 // ceil((NE + RR*127)/128)
#define EPADTOT (EGRID*BM)
#define STW 132                    // float2 row stride for smem hi/lo tiles

// ---------------- device scratch (static; no allocations) ----------------
__device__ __align__(16) float g_relw[NL*RR*DIM*DIM];
__device__ __align__(16) float g_h  [N_ENT*DIM];
__device__ __align__(16) float g_xa [N_ENT*DIM];
__device__ __align__(16) float g_xb [N_ENT*DIM];
__device__ __align__(16) float g_agg[N_ENT*DIM];
__device__ __align__(16) float g_xW [N_ENT*D3];
__device__ __align__(16) float g_hU [N_ENT*D3];
__device__ float g_deg[N_ENT];
__device__ float g_deginv[N_ENT];
__device__ int   g_perm[EPADTOT];
__device__ int   g_cnt[RR];
__device__ int   g_cur[RR];

// ---------------- helpers ----------------
// split x into tf32 hi/lo pair (both stored as f32 bit patterns)
__device__ __forceinline__ float2 hl(float x) {
    unsigned h; asm("cvt.rna.tf32.f32 %0, %1;" : "=r"(h) : "f"(x));
    float hf = __uint_as_float(h);
    float lo = x - hf;
    unsigned l; asm("cvt.rna.tf32.f32 %0, %1;" : "=r"(l) : "f"(lo));
    return make_float2(hf, __uint_as_float(l));
}

__device__ __forceinline__ void mma8(float* c,
                                     unsigned a0, unsigned a1, unsigned a2, unsigned a3,
                                     unsigned b0, unsigned b1) {
    asm volatile(
        "mma.sync.aligned.m16n8k8.row.col.f32.tf32.tf32.f32 "
        "{%0,%1,%2,%3}, {%4,%5,%6,%7}, {%8,%9}, {%0,%1,%2,%3};"
        : "+f"(c[0]), "+f"(c[1]), "+f"(c[2]), "+f"(c[3])
        : "r"(a0), "r"(a1), "r"(a2), "r"(a3), "r"(b0), "r"(b1));
}

__device__ __forceinline__ void red2(float* p, float a, float b) {
    asm volatile("red.global.add.v2.f32 [%0], {%1,%2};"
                 :: "l"(p), "f"(a), "f"(b) : "memory");
}

// 16-k slab of 3xTF32 mma: As2/Bs2 hold {hi,lo} float2 per element
__device__ __forceinline__ void tile_mma(const float2* __restrict__ As2,
                                         const float2* __restrict__ Bs2,
                                         float (*acc)[4][4],
                                         int wm, int wn, int grp, int qid) {
#pragma unroll
    for (int ks = 0; ks < 16; ks += 8) {
        float2 afr[4][4];
#pragma unroll
        for (int mi = 0; mi < 4; ++mi) {
            int mb = wm + mi*16 + grp;
            afr[mi][0] = As2[(ks+qid)*STW + mb];
            afr[mi][1] = As2[(ks+qid)*STW + mb + 8];
            afr[mi][2] = As2[(ks+qid+4)*STW + mb];
            afr[mi][3] = As2[(ks+qid+4)*STW + mb + 8];
        }
#pragma unroll
        for (int nj = 0; nj < 4; ++nj) {
            int nb = wn + nj*8 + grp;
            float2 bf0 = Bs2[(ks+qid)*STW + nb];
            float2 bf1 = Bs2[(ks+qid+4)*STW + nb];
            unsigned bh0 = __float_as_uint(bf0.x), bl0 = __float_as_uint(bf0.y);
            unsigned bh1 = __float_as_uint(bf1.x), bl1 = __float_as_uint(bf1.y);
#pragma unroll
            for (int mi = 0; mi < 4; ++mi) {
                unsigned ah0 = __float_as_uint(afr[mi][0].x), al0 = __float_as_uint(afr[mi][0].y);
                unsigned ah1 = __float_as_uint(afr[mi][1].x), al1 = __float_as_uint(afr[mi][1].y);
                unsigned ah2 = __float_as_uint(afr[mi][2].x), al2 = __float_as_uint(afr[mi][2].y);
                unsigned ah3 = __float_as_uint(afr[mi][3].x), al3 = __float_as_uint(afr[mi][3].y);
                mma8(acc[mi][nj], ah0, ah1, ah2, ah3, bh0, bh1);
                mma8(acc[mi][nj], al0, al1, al2, al3, bh0, bh1);
                mma8(acc[mi][nj], ah0, ah1, ah2, ah3, bl0, bl1);
            }
        }
    }
}

// ---------------- small utility kernels ----------------
__global__ void k_zerof(float* p, int n) {
    int i = blockIdx.x*blockDim.x + threadIdx.x;
    for (; i < n; i += gridDim.x*blockDim.x) p[i] = 0.f;
}
__global__ void k_filli(int* p, int n, int v) {
    int i = blockIdx.x*blockDim.x + threadIdx.x;
    for (; i < n; i += gridDim.x*blockDim.x) p[i] = v;
}
__global__ void k_copy(float* dst, const float* src, int n) {
    int i = blockIdx.x*blockDim.x + threadIdx.x;
    for (; i < n; i += gridDim.x*blockDim.x) dst[i] = src[i];
}

__global__ void k_relw(const float* __restrict__ basis, const float* __restrict__ coeff) {
    __shared__ float s_co[NL*RR*NB];
    int tid = threadIdx.x;
    for (int i = tid; i < NL*RR*NB; i += blockDim.x) s_co[i] = coeff[i];
    __syncthreads();
    int gid = blockIdx.x*blockDim.x + tid;
    if (gid >= NL*DIM*DIM) return;
    int l = gid / (DIM*DIM);
    int rem = gid % (DIM*DIM);
    int i = rem / DIM, o = rem % DIM;
    float acc[RR];
#pragma unroll
    for (int r = 0; r < RR; ++r) acc[r] = 0.f;
    for (int b = 0; b < NB; ++b) {
        float bv = basis[((l*NB + b)*DIM + i)*DIM + o];
#pragma unroll
        for (int r = 0; r < RR; ++r) acc[r] += s_co[(l*RR + r)*NB + b] * bv;
    }
    for (int r = 0; r < RR; ++r)
        g_relw[((l*RR + r)*DIM + i)*DIM + o] = acc[r];
}

__global__ void k_deg_acc(const int* __restrict__ rcv) {
    int i = blockIdx.x*blockDim.x + threadIdx.x;
    for (; i < NE; i += gridDim.x*blockDim.x) atomicAdd(&g_deg[rcv[i]], 1.f);
}
__global__ void k_deginv() {
    int i = blockIdx.x*blockDim.x + threadIdx.x;
    if (i < N_ENT) g_deginv[i] = 1.f / fmaxf(g_deg[i], 1.f);
}

__global__ void k_hist(const int* __restrict__ rel) {
    __shared__ int s_cnt[RR];
    int tid = threadIdx.x;
    if (tid < RR) s_cnt[tid] = 0;
    __syncthreads();
    int i = blockIdx.x*blockDim.x + tid;
    for (; i < NE; i += gridDim.x*blockDim.x) atomicAdd(&s_cnt[rel[i]], 1);
    __syncthreads();
    if (tid < RR) atomicAdd(&g_cnt[tid], s_cnt[tid]);
}
__global__ void k_scan() {
    int run = 0;
    for (int r = 0; r < RR; ++r) {
        g_cur[r] = run;
        run += ((g_cnt[r] + BM - 1) / BM) * BM;
    }
}
__global__ void k_scatter(const int* __restrict__ rel) {
    int i = blockIdx.x*blockDim.x + threadIdx.x;
    for (; i < NE; i += gridDim.x*blockDim.x) {
        int r = rel[i];
        int p = atomicAdd(&g_cur[r], 1);
        g_perm[p] = i;
    }
}

// ---------------- edge gather-GEMM-scatter (tensor core) ----------------
__global__ void __launch_bounds__(256)
k_edge_gemm(const float* __restrict__ x, const float* __restrict__ relw_l,
            const int* __restrict__ snd, const int* __restrict__ rcv,
            const int* __restrict__ relt) {
    __shared__ float2 As2[16*STW];
    __shared__ float2 Bs2[16*STW];
    __shared__ int s_src[BM], s_rcv[BM];
    __shared__ int s_rel;
    int tid = threadIdx.x;
    if (tid == 0) s_rel = -1;
    __syncthreads();
    if (tid < BM) {
        int e = g_perm[blockIdx.x*BM + tid];
        int sv = -1, rv = -1;
        if (e >= 0) { sv = snd[e]; rv = rcv[e]; s_rel = relt[e]; }
        s_src[tid] = sv; s_rcv[tid] = rv;
    }
    __syncthreads();
    int rel = s_rel;
    if (rel < 0) return;
    const float* W = relw_l + (size_t)rel * DIM * DIM;
    int n0 = blockIdx.y * BM;

    int lane = tid & 31, w = tid >> 5;
    int wm = (w & 1)*64, wn = (w >> 1)*32;
    int grp = lane >> 2, qid = lane & 3;

    float acc[4][4][4];
#pragma unroll
    for (int a = 0; a < 4; ++a)
#pragma unroll
        for (int b = 0; b < 4; ++b)
#pragma unroll
            for (int c = 0; c < 4; ++c) acc[a][b][c] = 0.f;

    for (int kt = 0; kt < 13; ++kt) {
        int k0 = kt * 16;
        for (int s = tid; s < 512; s += 256) {
            int m = s >> 2, kq = (s & 3) * 4;
            float4 v = make_float4(0.f,0.f,0.f,0.f);
            int src = s_src[m];
            if (src >= 0 && k0 + kq < DIM)
                v = *(const float4*)(x + (size_t)src*DIM + k0 + kq);
            As2[(kq+0)*STW + m] = hl(v.x);
            As2[(kq+1)*STW + m] = hl(v.y);
            As2[(kq+2)*STW + m] = hl(v.z);
            As2[(kq+3)*STW + m] = hl(v.w);
        }
        for (int s = tid; s < 512; s += 256) {
            int kr = s >> 5, c4 = (s & 31) * 4;
            float4 v = make_float4(0.f,0.f,0.f,0.f);
            int gk = k0 + kr, gc = n0 + c4;
            if (gk < DIM && gc < DIM)
                v = *(const float4*)(W + (size_t)gk*DIM + gc);
            Bs2[kr*STW + c4 + 0] = hl(v.x);
            Bs2[kr*STW + c4 + 1] = hl(v.y);
            Bs2[kr*STW + c4 + 2] = hl(v.z);
            Bs2[kr*STW + c4 + 3] = hl(v.w);
        }
        __syncthreads();
        tile_mma(As2, Bs2, acc, wm, wn, grp, qid);
        __syncthreads();
    }

    // scatter-add epilogue (mma C-fragment layout)
#pragma unroll
    for (int mi = 0; mi < 4; ++mi) {
        int r0 = wm + mi*16 + grp;
        int r1 = r0 + 8;
        int rv0 = s_rcv[r0], rv1 = s_rcv[r1];
#pragma unroll
        for (int nj = 0; nj < 4; ++nj) {
            int col = n0 + wn + nj*8 + qid*2;
            if (col >= DIM) continue;
            float* c = acc[mi][nj];
            if (rv0 >= 0) red2(g_agg + (size_t)rv0*DIM + col, c[0], c[1]);
            if (rv1 >= 0) red2(g_agg + (size_t)rv1*DIM + col, c[2], c[3]);
        }
    }
}

// ---------------- dense GEMM (tensor core) ----------------
// epi==1: C = relu(A@B + aux*deginv[row] + bias[col])  (N==DIM)
__global__ void __launch_bounds__(256)
k_gemm(const float* __restrict__ A, const float* __restrict__ B, float* __restrict__ C,
       int M, int N, int K, int epi,
       const float* __restrict__ aux, const float* __restrict__ dinv,
       const float* __restrict__ bias) {
    __shared__ float2 As2[16*STW];
    __shared__ float2 Bs2[16*STW];
    int tid = threadIdx.x;
    int m0 = blockIdx.x * BM;
    int n0 = blockIdx.y * BM;

    int lane = tid & 31, w = tid >> 5;
    int wm = (w & 1)*64, wn = (w >> 1)*32;
    int grp = lane >> 2, qid = lane & 3;

    float acc[4][4][4];
#pragma unroll
    for (int a = 0; a < 4; ++a)
#pragma unroll
        for (int b = 0; b < 4; ++b)
#pragma unroll
            for (int c = 0; c < 4; ++c) acc[a][b][c] = 0.f;

    int ktiles = (K + 15) / 16;
    for (int kt = 0; kt < ktiles; ++kt) {
        int k0 = kt * 16;
        for (int s = tid; s < 512; s += 256) {
            int m = s >> 2, kq = (s & 3) * 4;
            float4 v = make_float4(0.f,0.f,0.f,0.f);
            int gm = m0 + m;
            if (gm < M && k0 + kq < K)
                v = *(const float4*)(A + (size_t)gm*K + k0 + kq);
            As2[(kq+0)*STW + m] = hl(v.x);
            As2[(kq+1)*STW + m] = hl(v.y);
            As2[(kq+2)*STW + m] = hl(v.z);
            As2[(kq+3)*STW + m] = hl(v.w);
        }
        for (int s = tid; s < 512; s += 256) {
            int kr = s >> 5, c4 = (s & 31) * 4;
            float4 v = make_float4(0.f,0.f,0.f,0.f);
            int gk = k0 + kr, gc = n0 + c4;
            if (gk < K && gc < N)
                v = *(const float4*)(B + (size_t)gk*N + gc);
            Bs2[kr*STW + c4 + 0] = hl(v.x);
            Bs2[kr*STW + c4 + 1] = hl(v.y);
            Bs2[kr*STW + c4 + 2] = hl(v.z);
            Bs2[kr*STW + c4 + 3] = hl(v.w);
        }
        __syncthreads();
        tile_mma(As2, Bs2, acc, wm, wn, grp, qid);
        __syncthreads();
    }

#pragma unroll
    for (int mi = 0; mi < 4; ++mi) {
        int row0 = m0 + wm + mi*16 + grp;
        int row1 = row0 + 8;
#pragma unroll
        for (int nj = 0; nj < 4; ++nj) {
            int col = n0 + wn + nj*8 + qid*2;
            if (col >= N) continue;
            float* c = acc[mi][nj];
            float v0 = c[0], v1 = c[1], v2 = c[2], v3 = c[3];
            if (epi == 1) {
                float bc0 = bias[col], bc1 = bias[col+1];
                if (row0 < M) {
                    float di = dinv[row0];
                    float2 a = *(const float2*)(aux + (size_t)row0*DIM + col);
                    v0 = fmaxf(v0 + a.x*di + bc0, 0.f);
                    v1 = fmaxf(v1 + a.y*di + bc1, 0.f);
                }
                if (row1 < M) {
                    float di = dinv[row1];
                    float2 a = *(const float2*)(aux + (size_t)row1*DIM + col);
                    v2 = fmaxf(v2 + a.x*di + bc0, 0.f);
                    v3 = fmaxf(v3 + a.y*di + bc1, 0.f);
                }
            }
            if (row0 < M) *(float2*)(C + (size_t)row0*N + col) = make_float2(v0, v1);
            if (row1 < M) *(float2*)(C + (size_t)row1*N + col) = make_float2(v2, v3);
        }
    }
}

__device__ __forceinline__ float sigf(float x) { return 1.f / (1.f + expf(-x)); }

__global__ void k_gru(const float* __restrict__ bg) {
    int idx = blockIdx.x*blockDim.x + threadIdx.x;
    if (idx >= N_ENT*DIM) return;
    int n = idx / DIM, c = idx % DIM;
    size_t b = (size_t)n*D3;
    float r  = sigf(g_xW[b + c]        + g_hU[b + c]        + bg[c]);
    float z  = sigf(g_xW[b + DIM + c]  + g_hU[b + DIM + c]  + bg[DIM + c]);
    float hu3 = g_hU[b + 2*DIM + c];
    float ht = tanhf(g_xW[b + 2*DIM + c] + hu3 + bg[2*DIM + c] + r * hu3);
    float h0 = g_h[idx];
    g_h[idx] = (1.f - z)*h0 + z*ht;
}

// scorer: out[q] = relu([h_s, rel, h_o] @ fc1 + b1) @ fc2 + b2
__global__ void __launch_bounds__(256)
k_score(const int* __restrict__ triples, const float* __restrict__ rel_emb,
        const float* __restrict__ fc1, const float* __restrict__ b1,
        const float* __restrict__ fc2, const float* __restrict__ fc2b,
        float* __restrict__ out) {
    __shared__ float As[32][8];
    __shared__ float Bs[8][HID];
    __shared__ int s_s[32], s_r[32], s_o[32];
    int tid = threadIdx.x;
    int qbase = blockIdx.x * 32;
    if (tid < 32) {
        s_s[tid] = triples[(qbase + tid)*3 + 0];
        s_r[tid] = triples[(qbase + tid)*3 + 1];
        s_o[tid] = triples[(qbase + tid)*3 + 2];
    }
    __syncthreads();
    int w = tid >> 5, lane = tid & 31;
    float acc[4][8];
#pragma unroll
    for (int i = 0; i < 4; ++i)
#pragma unroll
        for (int j = 0; j < 8; ++j) acc[i][j] = 0.f;

    for (int k0 = 0; k0 < D3; k0 += 8) {
        {
            int qi = tid >> 3, kk = tid & 7, k = k0 + kk;
            float v;
            if (k < DIM)            v = g_h[(size_t)s_s[qi]*DIM + k];
            else if (k < 2*DIM)     v = rel_emb[(size_t)s_r[qi]*DIM + (k - DIM)];
            else                    v = g_h[(size_t)s_o[qi]*DIM + (k - 2*DIM)];
            As[qi][kk] = v;
        }
        {
            int kr = tid >> 5, cb = tid & 31;
#pragma unroll
            for (int j = 0; j < 8; ++j)
                Bs[kr][cb + 32*j] = fc1[(size_t)(k0 + kr)*HID + cb + 32*j];
        }
        __syncthreads();
#pragma unroll
        for (int kk = 0; kk < 8; ++kk) {
#pragma unroll
            for (int i = 0; i < 4; ++i) {
                float a = As[w*4 + i][kk];
#pragma unroll
                for (int j = 0; j < 8; ++j)
                    acc[i][j] += a * Bs[kk][lane + 32*j];
            }
        }
        __syncthreads();
    }
#pragma unroll
    for (int i = 0; i < 4; ++i) {
        float p = 0.f;
#pragma unroll
        for (int j = 0; j < 8; ++j) {
            int col = lane + 32*j;
            float hv = fmaxf(acc[i][j] + b1[col], 0.f);
            p += hv * fc2[col];
        }
#pragma unroll
        for (int off = 16; off > 0; off >>= 1)
            p += __shfl_down_sync(0xffffffffu, p, off);
        if (lane == 0) out[qbase + w*4 + i] = p + fc2b[0];
    }
}

// ---------------- host ----------------
extern "C" void kernel_launch(void* const* d_in, const int* in_sizes, int n_in,
                              void* d_out, int out_size) {
    const float* entity_emb = (const float*)d_in[0];
    const float* basis      = (const float*)d_in[1];
    const float* coeff      = (const float*)d_in[2];
    const float* self_w     = (const float*)d_in[3];
    const float* bias       = (const float*)d_in[4];
    const float* W_gates    = (const float*)d_in[5];
    const float* U_gates    = (const float*)d_in[6];
    const float* b_gates    = (const float*)d_in[7];
    const float* rel_emb    = (const float*)d_in[8];
    const float* fc1        = (const float*)d_in[9];
    const float* fc1_b      = (const float*)d_in[10];
    const float* fc2        = (const float*)d_in[11];
    const float* fc2_b      = (const float*)d_in[12];
    const int*   senders    = (const int*)d_in[13];
    const int*   receivers  = (const int*)d_in[14];
    const int*   rel_types  = (const int*)d_in[15];
    const int*   triples    = (const int*)d_in[16];
    float* out = (float*)d_out;

    float *p_relw, *p_h, *p_xa, *p_xb, *p_agg, *p_xW, *p_hU, *p_deg, *p_dinv;
    int *p_perm, *p_cnt;
    cudaGetSymbolAddress((void**)&p_relw, g_relw);
    cudaGetSymbolAddress((void**)&p_h,    g_h);
    cudaGetSymbolAddress((void**)&p_xa,   g_xa);
    cudaGetSymbolAddress((void**)&p_xb,   g_xb);
    cudaGetSymbolAddress((void**)&p_agg,  g_agg);
    cudaGetSymbolAddress((void**)&p_xW,   g_xW);
    cudaGetSymbolAddress((void**)&p_hU,   g_hU);
    cudaGetSymbolAddress((void**)&p_deg,  g_deg);
    cudaGetSymbolAddress((void**)&p_dinv, g_deginv);
    cudaGetSymbolAddress((void**)&p_perm, g_perm);
    cudaGetSymbolAddress((void**)&p_cnt,  g_cnt);

    k_relw<<<(NL*DIM*DIM + 255)/256, 256>>>(basis, coeff);
    k_copy<<<1024, 256>>>(p_h, entity_emb, N_ENT*DIM);

    for (int t = 0; t < NT; ++t) {
        const int* snd = senders   + (size_t)t*NE;
        const int* rcv = receivers + (size_t)t*NE;
        const int* rlt = rel_types + (size_t)t*NE;

        k_zerof<<<256, 256>>>(p_deg, N_ENT);
        k_deg_acc<<<512, 256>>>(rcv);
        k_deginv<<<(N_ENT + 255)/256, 256>>>();

        k_filli<<<512, 256>>>(p_perm, EPADTOT, -1);
        k_filli<<<1, 32>>>(p_cnt, RR, 0);
        k_hist<<<256, 256>>>(rlt);
        k_scan<<<1, 1>>>();
        k_scatter<<<512, 256>>>(rlt);

        k_copy<<<1024, 256>>>(p_xa, p_h, N_ENT*DIM);
        float* xin = p_xa;
        for (int l = 0; l < NL; ++l) {
            float* xout = (l == 0) ? p_xb : p_xa;
            k_zerof<<<1024, 256>>>(p_agg, N_ENT*DIM);
            k_edge_gemm<<<dim3(EGRID, 2), 256>>>(xin, p_relw + (size_t)l*RR*DIM*DIM,
                                                 snd, rcv, rlt);
            k_gemm<<<dim3((N_ENT + BM - 1)/BM, (DIM + BM - 1)/BM), 256>>>(
                xin, self_w + (size_t)l*DIM*DIM, xout,
                N_ENT, DIM, DIM, 1, p_agg, p_dinv, bias + (size_t)l*DIM);
            xin = xout;
        }
        k_gemm<<<dim3((N_ENT + BM - 1)/BM, (D3 + BM - 1)/BM), 256>>>(
            xin, W_gates, p_xW, N_ENT, D3, DIM, 0, nullptr, nullptr, nullptr);
        k_gemm<<<dim3((N_ENT + BM - 1)/BM, (D3 + BM - 1)/BM), 256>>>(
            p_h, U_gates, p_hU, N_ENT, D3, DIM, 0, nullptr, nullptr, nullptr);
        k_gru<<<(N_ENT*DIM + 255)/256, 256>>>(b_gates);
    }

    k_score<<<NQ/32, 256>>>(triples, rel_emb, fc1, fc1_b, fc2, fc2_b, out);
}

// round 5
// speedup vs baseline: 1.6451x; 1.6451x over previous
#include <cuda_runtime.h>
#include <cuda_fp16.h>
#include <math.h>
#include <stdint.h>

#define N_ENT 20000
#define DIM   200
#define RR    20
#define NB    20
#define NL    2
#define NT    2
#define NE    250000
#define NQ    8192
#define HID   256
#define D3    600

#define BM 128
#define EGRID 1973
#define EPADTOT (EGRID*BM)
#define MTILES 157            // ceil(20000/128)
#define GNPAD 640             // gates N padded
#define XROW 512              // halves per row: 256 hi + 256 lo
#define NSLAB 7               // 7 * 32 = 224 >= 200 (K padded)

#define XS 64.0f              // activation pre-scale (2^6)
#define WS 2048.0f            // weight pre-scale (2^11)
#define SCALE_INV (1.0f/131072.0f)   // 2^-17

// ---------------- device scratch ----------------
__device__ __align__(16) float g_relw[NL*RR*DIM*DIM];
__device__ __align__(16) float g_h  [N_ENT*DIM];
__device__ __align__(16) float g_agg[N_ENT*DIM];
__device__ __align__(16) float g_xW [N_ENT*D3];
__device__ __align__(16) float g_hU [N_ENT*D3];
__device__ float g_deg[N_ENT];
__device__ float g_deginv[N_ENT];
__device__ int   g_perm[EPADTOT];
__device__ int   g_cnt[RR];
__device__ int   g_cur[RR];
// fp16 scaled hi/lo split operands
__device__ __align__(16) __half g_hs [N_ENT*XROW];
__device__ __align__(16) __half g_xs1[(size_t)N_ENT*XROW];
__device__ __align__(16) __half g_xs2[(size_t)N_ENT*XROW];
__device__ __align__(16) __half g_ws [(size_t)NL*RR*256*XROW];   // rel weights (transposed rows n)
__device__ __align__(16) __half g_sws[(size_t)NL*256*XROW];
__device__ __align__(16) __half g_gws[(size_t)GNPAD*XROW];
__device__ __align__(16) __half g_gus[(size_t)GNPAD*XROW];

// ---------------- helpers ----------------
__device__ __forceinline__ void mma16(float* c, const uint32_t* a, const uint32_t* b) {
    asm volatile(
        "mma.sync.aligned.m16n8k16.row.col.f32.f16.f16.f32 "
        "{%0,%1,%2,%3}, {%4,%5,%6,%7}, {%8,%9}, {%0,%1,%2,%3};"
        : "+f"(c[0]), "+f"(c[1]), "+f"(c[2]), "+f"(c[3])
        : "r"(a[0]), "r"(a[1]), "r"(a[2]), "r"(a[3]), "r"(b[0]), "r"(b[1]));
}
__device__ __forceinline__ void red2(float* p, float a, float b) {
    asm volatile("red.global.add.v2.f32 [%0], {%1,%2};"
                 :: "l"(p), "f"(a), "f"(b) : "memory");
}
__device__ __forceinline__ float sigf(float x) { return 1.f / (1.f + expf(-x)); }

// ---------------- small utility kernels ----------------
__global__ void k_zerof(float* p, int n) {
    int i = blockIdx.x*blockDim.x + threadIdx.x;
    for (; i < n; i += gridDim.x*blockDim.x) p[i] = 0.f;
}
__global__ void k_filli(int* p, int n, int v) {
    int i = blockIdx.x*blockDim.x + threadIdx.x;
    for (; i < n; i += gridDim.x*blockDim.x) p[i] = v;
}
__global__ void k_copy(float* dst, const float* src, int n) {
    int i = blockIdx.x*blockDim.x + threadIdx.x;
    for (; i < n; i += gridDim.x*blockDim.x) dst[i] = src[i];
}

__global__ void k_relw(const float* __restrict__ basis, const float* __restrict__ coeff) {
    __shared__ float s_co[NL*RR*NB];
    int tid = threadIdx.x;
    for (int i = tid; i < NL*RR*NB; i += blockDim.x) s_co[i] = coeff[i];
    __syncthreads();
    int gid = blockIdx.x*blockDim.x + tid;
    if (gid >= NL*DIM*DIM) return;
    int l = gid / (DIM*DIM);
    int rem = gid % (DIM*DIM);
    int i = rem / DIM, o = rem % DIM;
    float acc[RR];
#pragma unroll
    for (int r = 0; r < RR; ++r) acc[r] = 0.f;
    for (int b = 0; b < NB; ++b) {
        float bv = basis[((l*NB + b)*DIM + i)*DIM + o];
#pragma unroll
        for (int r = 0; r < RR; ++r) acc[r] += s_co[(l*RR + r)*NB + b] * bv;
    }
    for (int r = 0; r < RR; ++r)
        g_relw[((l*RR + r)*DIM + i)*DIM + o] = acc[r];
}

// transpose + scaled fp16 hi/lo split: dst[b][n][k] = WS * src[b][k][n]
__global__ void k_splitw(const float* __restrict__ src, __half* __restrict__ dst,
                         int Nsrc, int Nvalid, size_t sstride, size_t dstride) {
    int b = blockIdx.z;
    int idx = blockIdx.x*blockDim.x + threadIdx.x;
    int n = idx >> 8, k = idx & 255;
    float v = 0.f;
    if (n < Nvalid && k < DIM) v = src[b*sstride + (size_t)k*Nsrc + n] * WS;
    __half hi = __float2half_rn(v);
    float lo = v - __half2float(hi);
    dst[b*dstride + (size_t)n*XROW + k]       = hi;
    dst[b*dstride + (size_t)n*XROW + 256 + k] = __float2half_rn(lo);
}

// scaled fp16 hi/lo split of entity rows
__global__ void k_splitx(const float* __restrict__ src, __half* __restrict__ dst) {
    int idx = blockIdx.x*blockDim.x + threadIdx.x;
    if (idx >= N_ENT*256) return;
    int n = idx >> 8, c = idx & 255;
    float v = (c < DIM) ? src[(size_t)n*DIM + c] * XS : 0.f;
    __half hi = __float2half_rn(v);
    float lo = v - __half2float(hi);
    dst[(size_t)n*XROW + c]       = hi;
    dst[(size_t)n*XROW + 256 + c] = __float2half_rn(lo);
}

__global__ void k_deg_acc(const int* __restrict__ rcv) {
    int i = blockIdx.x*blockDim.x + threadIdx.x;
    for (; i < NE; i += gridDim.x*blockDim.x) atomicAdd(&g_deg[rcv[i]], 1.f);
}
__global__ void k_deginv() {
    int i = blockIdx.x*blockDim.x + threadIdx.x;
    if (i < N_ENT) g_deginv[i] = 1.f / fmaxf(g_deg[i], 1.f);
}
__global__ void k_hist(const int* __restrict__ rel) {
    __shared__ int s_cnt[RR];
    int tid = threadIdx.x;
    if (tid < RR) s_cnt[tid] = 0;
    __syncthreads();
    int i = blockIdx.x*blockDim.x + tid;
    for (; i < NE; i += gridDim.x*blockDim.x) atomicAdd(&s_cnt[rel[i]], 1);
    __syncthreads();
    if (tid < RR) atomicAdd(&g_cnt[tid], s_cnt[tid]);
}
__global__ void k_scan() {
    int run = 0;
    for (int r = 0; r < RR; ++r) {
        g_cur[r] = run;
        run += ((g_cnt[r] + BM - 1) / BM) * BM;
    }
}
__global__ void k_scatter(const int* __restrict__ rel) {
    int i = blockIdx.x*blockDim.x + threadIdx.x;
    for (; i < NE; i += gridDim.x*blockDim.x) {
        int r = rel[i];
        int p = atomicAdd(&g_cur[r], 1);
        g_perm[p] = i;
    }
}

// ---------------- core fp16 3-pass mma mainloop (macro-free inline) ----------------
// smem tiles: [part][k2 local 0..15][136] of uint32 (=half2 pairs along k)

// edge gather-GEMM-scatter: agg[rcv[e]] += x[snd[e]] @ W_rel
__global__ void __launch_bounds__(256)
k_edge(const __half* __restrict__ xs, const __half* __restrict__ wsl,
       const int* __restrict__ snd, const int* __restrict__ rcv,
       const int* __restrict__ relt) {
    __shared__ uint32_t As2[2][16][136];
    __shared__ uint32_t Bs2[2][16][136];
    __shared__ int s_src[BM], s_rcv[BM];
    int tid = threadIdx.x, lane = tid & 31, w = tid >> 5;

    int e0 = g_perm[blockIdx.x*BM];
    if (e0 < 0) return;
    int rel = relt[e0];
    if (tid < BM) {
        int e = g_perm[blockIdx.x*BM + tid];
        int sv = 0, rv = -1;
        if (e >= 0) { sv = snd[e]; rv = rcv[e]; }
        s_src[tid] = sv; s_rcv[tid] = rv;
    }
    __syncthreads();

    const __half* wr = wsl + (size_t)rel * (256*XROW);
    int n0 = blockIdx.y * BM;
    int wm = (w & 1)*64, wn = (w >> 1)*32;
    int grp = lane >> 2, qid = lane & 3;

    float acc[4][4][4];
#pragma unroll
    for (int a = 0; a < 4; ++a)
#pragma unroll
        for (int b = 0; b < 4; ++b)
#pragma unroll
            for (int c = 0; c < 4; ++c) acc[a][b][c] = 0.f;

    for (int s = 0; s < NSLAB; ++s) {
        int k2b = s*16;
        for (int j = tid; j < 1024; j += 256) {        // A: 2 parts x 128 rows x 4 chunks
            int p = j >> 9, q = j & 511, m = q & 127, c = q >> 7;
            int k2 = k2b + c*4;
            uint4 v = *(const uint4*)(xs + (size_t)s_src[m]*XROW + p*256 + 2*k2);
            int lk = c*4;
            As2[p][lk+0][m] = v.x; As2[p][lk+1][m] = v.y;
            As2[p][lk+2][m] = v.z; As2[p][lk+3][m] = v.w;
        }
        for (int j = tid; j < 1024; j += 256) {        // B: 2 parts x 128 rows x 4 chunks
            int p = j >> 9, q = j & 511, n = q & 127, c = q >> 7;
            int k2 = k2b + c*4;
            uint4 v = *(const uint4*)(wr + (size_t)(n0 + n)*XROW + p*256 + 2*k2);
            int lk = c*4;
            Bs2[p][lk+0][n] = v.x; Bs2[p][lk+1][n] = v.y;
            Bs2[p][lk+2][n] = v.z; Bs2[p][lk+3][n] = v.w;
        }
        __syncthreads();
#pragma unroll
        for (int kk = 0; kk < 2; ++kk) {
            int kq0 = kk*8 + qid, kq1 = kq0 + 4;
            uint32_t aH[4][4], aL[4][4], bH[4][2], bL[4][2];
#pragma unroll
            for (int mi = 0; mi < 4; ++mi) {
                int mb = wm + mi*16 + grp;
                aH[mi][0] = As2[0][kq0][mb];   aH[mi][1] = As2[0][kq0][mb+8];
                aH[mi][2] = As2[0][kq1][mb];   aH[mi][3] = As2[0][kq1][mb+8];
                aL[mi][0] = As2[1][kq0][mb];   aL[mi][1] = As2[1][kq0][mb+8];
                aL[mi][2] = As2[1][kq1][mb];   aL[mi][3] = As2[1][kq1][mb+8];
            }
#pragma unroll
            for (int nj = 0; nj < 4; ++nj) {
                int nb = wn + nj*8 + grp;
                bH[nj][0] = Bs2[0][kq0][nb];   bH[nj][1] = Bs2[0][kq1][nb];
                bL[nj][0] = Bs2[1][kq0][nb];   bL[nj][1] = Bs2[1][kq1][nb];
            }
#pragma unroll
            for (int mi = 0; mi < 4; ++mi)
#pragma unroll
                for (int nj = 0; nj < 4; ++nj) {
                    mma16(acc[mi][nj], aH[mi], bH[nj]);
                    mma16(acc[mi][nj], aL[mi], bH[nj]);
                    mma16(acc[mi][nj], aH[mi], bL[nj]);
                }
        }
        __syncthreads();
    }
    // scatter-add epilogue
#pragma unroll
    for (int mi = 0; mi < 4; ++mi) {
        int r0 = wm + mi*16 + grp;
        int rv0 = s_rcv[r0], rv1 = s_rcv[r0 + 8];
#pragma unroll
        for (int nj = 0; nj < 4; ++nj) {
            int col = n0 + wn + nj*8 + qid*2;
            if (col >= DIM) continue;
            float* c = acc[mi][nj];
            if (rv0 >= 0) red2(g_agg + (size_t)rv0*DIM + col, c[0]*SCALE_INV, c[1]*SCALE_INV);
            if (rv1 >= 0) red2(g_agg + (size_t)rv1*DIM + col, c[2]*SCALE_INV, c[3]*SCALE_INV);
        }
    }
}

// dense GEMM: D = A @ B^T (B rows = output cols, transposed-split layout)
// mode 0: C[m][col] = D*SCALE_INV               (guard col < Nvalid)
// mode 1: out_xs = split(XS * relu(D*SCALE_INV + agg*dinv + bias)), zero for col >= DIM
__global__ void __launch_bounds__(256)
k_dense(const __half* __restrict__ Axs, const __half* __restrict__ Bws,
        int M, int mode, int Nvalid,
        float* __restrict__ C, int ldC,
        const float* __restrict__ agg, const float* __restrict__ dinv,
        const float* __restrict__ bias, __half* __restrict__ out_xs) {
    __shared__ uint32_t As2[2][16][136];
    __shared__ uint32_t Bs2[2][16][136];
    int tid = threadIdx.x, lane = tid & 31, w = tid >> 5;
    int m0 = blockIdx.x * BM;
    int n0 = blockIdx.y * BM;
    int wm = (w & 1)*64, wn = (w >> 1)*32;
    int grp = lane >> 2, qid = lane & 3;

    float acc[4][4][4];
#pragma unroll
    for (int a = 0; a < 4; ++a)
#pragma unroll
        for (int b = 0; b < 4; ++b)
#pragma unroll
            for (int c = 0; c < 4; ++c) acc[a][b][c] = 0.f;

    for (int s = 0; s < NSLAB; ++s) {
        int k2b = s*16;
        for (int j = tid; j < 1024; j += 256) {
            int p = j >> 9, q = j & 511, m = q & 127, c = q >> 7;
            int k2 = k2b + c*4;
            int gm = m0 + m; if (gm >= M) gm = 0;
            uint4 v = *(const uint4*)(Axs + (size_t)gm*XROW + p*256 + 2*k2);
            int lk = c*4;
            As2[p][lk+0][m] = v.x; As2[p][lk+1][m] = v.y;
            As2[p][lk+2][m] = v.z; As2[p][lk+3][m] = v.w;
        }
        for (int j = tid; j < 1024; j += 256) {
            int p = j >> 9, q = j & 511, n = q & 127, c = q >> 7;
            int k2 = k2b + c*4;
            uint4 v = *(const uint4*)(Bws + (size_t)(n0 + n)*XROW + p*256 + 2*k2);
            int lk = c*4;
            Bs2[p][lk+0][n] = v.x; Bs2[p][lk+1][n] = v.y;
            Bs2[p][lk+2][n] = v.z; Bs2[p][lk+3][n] = v.w;
        }
        __syncthreads();
#pragma unroll
        for (int kk = 0; kk < 2; ++kk) {
            int kq0 = kk*8 + qid, kq1 = kq0 + 4;
            uint32_t aH[4][4], aL[4][4], bH[4][2], bL[4][2];
#pragma unroll
            for (int mi = 0; mi < 4; ++mi) {
                int mb = wm + mi*16 + grp;
                aH[mi][0] = As2[0][kq0][mb];   aH[mi][1] = As2[0][kq0][mb+8];
                aH[mi][2] = As2[0][kq1][mb];   aH[mi][3] = As2[0][kq1][mb+8];
                aL[mi][0] = As2[1][kq0][mb];   aL[mi][1] = As2[1][kq0][mb+8];
                aL[mi][2] = As2[1][kq1][mb];   aL[mi][3] = As2[1][kq1][mb+8];
            }
#pragma unroll
            for (int nj = 0; nj < 4; ++nj) {
                int nb = wn + nj*8 + grp;
                bH[nj][0] = Bs2[0][kq0][nb];   bH[nj][1] = Bs2[0][kq1][nb];
                bL[nj][0] = Bs2[1][kq0][nb];   bL[nj][1] = Bs2[1][kq1][nb];
            }
#pragma unroll
            for (int mi = 0; mi < 4; ++mi)
#pragma unroll
                for (int nj = 0; nj < 4; ++nj) {
                    mma16(acc[mi][nj], aH[mi], bH[nj]);
                    mma16(acc[mi][nj], aL[mi], bH[nj]);
                    mma16(acc[mi][nj], aH[mi], bL[nj]);
                }
        }
        __syncthreads();
    }

#pragma unroll
    for (int mi = 0; mi < 4; ++mi) {
        int r0 = m0 + wm + mi*16 + grp;
        int r1 = r0 + 8;
#pragma unroll
        for (int nj = 0; nj < 4; ++nj) {
            int col = n0 + wn + nj*8 + qid*2;
            float* c = acc[mi][nj];
            if (mode == 0) {
                if (col >= Nvalid) continue;
                if (r0 < M) *(float2*)(C + (size_t)r0*ldC + col) =
                    make_float2(c[0]*SCALE_INV, c[1]*SCALE_INV);
                if (r1 < M) *(float2*)(C + (size_t)r1*ldC + col) =
                    make_float2(c[2]*SCALE_INV, c[3]*SCALE_INV);
            } else {
#pragma unroll
                for (int h = 0; h < 2; ++h) {
                    int row = h ? r1 : r0;
                    if (row >= M) continue;
                    float v0 = 0.f, v1 = 0.f;
                    if (col < DIM) {
                        float dv = dinv[row];
                        float a0 = agg[(size_t)row*DIM + col]*dv + bias[col];
                        float a1 = agg[(size_t)row*DIM + col + 1]*dv + bias[col + 1];
                        v0 = fmaxf(c[h*2+0]*SCALE_INV + a0, 0.f) * XS;
                        v1 = fmaxf(c[h*2+1]*SCALE_INV + a1, 0.f) * XS;
                    }
                    __half h0 = __float2half_rn(v0), h1 = __float2half_rn(v1);
                    float l0 = v0 - __half2float(h0), l1 = v1 - __half2float(h1);
                    *(__half2*)(out_xs + (size_t)row*XROW + col) = __halves2half2(h0, h1);
                    *(__half2*)(out_xs + (size_t)row*XROW + 256 + col) =
                        __halves2half2(__float2half_rn(l0), __float2half_rn(l1));
                }
            }
        }
    }
}

__global__ void k_gru(const float* __restrict__ bg) {
    int idx = blockIdx.x*blockDim.x + threadIdx.x;
    if (idx >= N_ENT*DIM) return;
    int n = idx / DIM, c = idx % DIM;
    size_t b = (size_t)n*D3;
    float r  = sigf(g_xW[b + c]        + g_hU[b + c]        + bg[c]);
    float z  = sigf(g_xW[b + DIM + c]  + g_hU[b + DIM + c]  + bg[DIM + c]);
    float hu3 = g_hU[b + 2*DIM + c];
    float ht = tanhf(g_xW[b + 2*DIM + c] + hu3 + bg[2*DIM + c] + r * hu3);
    float h0 = g_h[idx];
    float hn = (1.f - z)*h0 + z*ht;
    g_h[idx] = hn;
    float X = hn * XS;
    __half hi = __float2half_rn(X);
    float lo = X - __half2float(hi);
    g_hs[(size_t)n*XROW + c]       = hi;
    g_hs[(size_t)n*XROW + 256 + c] = __float2half_rn(lo);
}

// scorer: out[q] = relu([h_s, rel, h_o] @ fc1 + b1) @ fc2 + b2
__global__ void __launch_bounds__(256)
k_score(const int* __restrict__ triples, const float* __restrict__ rel_emb,
        const float* __restrict__ fc1, const float* __restrict__ b1,
        const float* __restrict__ fc2, const float* __restrict__ fc2b,
        float* __restrict__ out) {
    __shared__ float As[32][8];
    __shared__ float Bs[8][HID];
    __shared__ int s_s[32], s_r[32], s_o[32];
    int tid = threadIdx.x;
    int qbase = blockIdx.x * 32;
    if (tid < 32) {
        s_s[tid] = triples[(qbase + tid)*3 + 0];
        s_r[tid] = triples[(qbase + tid)*3 + 1];
        s_o[tid] = triples[(qbase + tid)*3 + 2];
    }
    __syncthreads();
    int w = tid >> 5, lane = tid & 31;
    float acc[4][8];
#pragma unroll
    for (int i = 0; i < 4; ++i)
#pragma unroll
        for (int j = 0; j < 8; ++j) acc[i][j] = 0.f;

    for (int k0 = 0; k0 < D3; k0 += 8) {
        {
            int qi = tid >> 3, kk = tid & 7, k = k0 + kk;
            float v;
            if (k < DIM)            v = g_h[(size_t)s_s[qi]*DIM + k];
            else if (k < 2*DIM)     v = rel_emb[(size_t)s_r[qi]*DIM + (k - DIM)];
            else                    v = g_h[(size_t)s_o[qi]*DIM + (k - 2*DIM)];
            As[qi][kk] = v;
        }
        {
            int kr = tid >> 5, cb = tid & 31;
#pragma unroll
            for (int j = 0; j < 8; ++j)
                Bs[kr][cb + 32*j] = fc1[(size_t)(k0 + kr)*HID + cb + 32*j];
        }
        __syncthreads();
#pragma unroll
        for (int kk = 0; kk < 8; ++kk) {
#pragma unroll
            for (int i = 0; i < 4; ++i) {
                float a = As[w*4 + i][kk];
#pragma unroll
                for (int j = 0; j < 8; ++j)
                    acc[i][j] += a * Bs[kk][lane + 32*j];
            }
        }
        __syncthreads();
    }
#pragma unroll
    for (int i = 0; i < 4; ++i) {
        float p = 0.f;
#pragma unroll
        for (int j = 0; j < 8; ++j) {
            int col = lane + 32*j;
            float hv = fmaxf(acc[i][j] + b1[col], 0.f);
            p += hv * fc2[col];
        }
#pragma unroll
        for (int off = 16; off > 0; off >>= 1)
            p += __shfl_down_sync(0xffffffffu, p, off);
        if (lane == 0) out[qbase + w*4 + i] = p + fc2b[0];
    }
}

// ---------------- host ----------------
extern "C" void kernel_launch(void* const* d_in, const int* in_sizes, int n_in,
                              void* d_out, int out_size) {
    const float* entity_emb = (const float*)d_in[0];
    const float* basis      = (const float*)d_in[1];
    const float* coeff      = (const float*)d_in[2];
    const float* self_w     = (const float*)d_in[3];
    const float* bias       = (const float*)d_in[4];
    const float* W_gates    = (const float*)d_in[5];
    const float* U_gates    = (const float*)d_in[6];
    const float* b_gates    = (const float*)d_in[7];
    const float* rel_emb    = (const float*)d_in[8];
    const float* fc1        = (const float*)d_in[9];
    const float* fc1_b      = (const float*)d_in[10];
    const float* fc2        = (const float*)d_in[11];
    const float* fc2_b      = (const float*)d_in[12];
    const int*   senders    = (const int*)d_in[13];
    const int*   receivers  = (const int*)d_in[14];
    const int*   rel_types  = (const int*)d_in[15];
    const int*   triples    = (const int*)d_in[16];
    float* out = (float*)d_out;

    float *p_relw, *p_h, *p_agg, *p_deg, *p_dinv, *p_xW, *p_hU;
    int *p_perm, *p_cnt;
    __half *p_hs, *p_xs1, *p_xs2, *p_ws, *p_sws, *p_gws, *p_gus;
    cudaGetSymbolAddress((void**)&p_relw, g_relw);
    cudaGetSymbolAddress((void**)&p_h,    g_h);
    cudaGetSymbolAddress((void**)&p_agg,  g_agg);
    cudaGetSymbolAddress((void**)&p_deg,  g_deg);
    cudaGetSymbolAddress((void**)&p_dinv, g_deginv);
    cudaGetSymbolAddress((void**)&p_perm, g_perm);
    cudaGetSymbolAddress((void**)&p_cnt,  g_cnt);
    cudaGetSymbolAddress((void**)&p_xW,   g_xW);
    cudaGetSymbolAddress((void**)&p_hU,   g_hU);
    cudaGetSymbolAddress((void**)&p_hs,   g_hs);
    cudaGetSymbolAddress((void**)&p_xs1,  g_xs1);
    cudaGetSymbolAddress((void**)&p_xs2,  g_xs2);
    cudaGetSymbolAddress((void**)&p_ws,   g_ws);
    cudaGetSymbolAddress((void**)&p_sws,  g_sws);
    cudaGetSymbolAddress((void**)&p_gws,  g_gws);
    cudaGetSymbolAddress((void**)&p_gus,  g_gus);

    // weight precompute
    k_relw<<<(NL*DIM*DIM + 255)/256, 256>>>(basis, coeff);
    k_splitw<<<dim3(256, 1, NL*RR), 256>>>(p_relw, p_ws, DIM, DIM,
                                           (size_t)DIM*DIM, (size_t)256*XROW);
    k_splitw<<<dim3(256, 1, NL), 256>>>(self_w, p_sws, DIM, DIM,
                                        (size_t)DIM*DIM, (size_t)256*XROW);
    k_splitw<<<dim3(GNPAD, 1, 1), 256>>>(W_gates, p_gws, D3, D3, 0, 0);
    k_splitw<<<dim3(GNPAD, 1, 1), 256>>>(U_gates, p_gus, D3, D3, 0, 0);
    k_splitx<<<(N_ENT*256 + 255)/256, 256>>>(entity_emb, p_hs);
    k_copy<<<1024, 256>>>(p_h, entity_emb, N_ENT*DIM);

    for (int t = 0; t < NT; ++t) {
        const int* snd = senders   + (size_t)t*NE;
        const int* rcv = receivers + (size_t)t*NE;
        const int* rlt = rel_types + (size_t)t*NE;

        k_zerof<<<256, 256>>>(p_deg, N_ENT);
        k_deg_acc<<<512, 256>>>(rcv);
        k_deginv<<<(N_ENT + 255)/256, 256>>>();

        k_filli<<<512, 256>>>(p_perm, EPADTOT, -1);
        k_filli<<<1, 32>>>(p_cnt, RR, 0);
        k_hist<<<256, 256>>>(rlt);
        k_scan<<<1, 1>>>();
        k_scatter<<<512, 256>>>(rlt);

        const __half* xin = p_hs;
        __half* xout[2] = { p_xs1, p_xs2 };
        for (int l = 0; l < NL; ++l) {
            k_zerof<<<1024, 256>>>(p_agg, N_ENT*DIM);
            k_edge<<<dim3(EGRID, 2), 256>>>(xin, p_ws + (size_t)l*RR*256*XROW,
                                            snd, rcv, rlt);
            k_dense<<<dim3(MTILES, 2), 256>>>(
                xin, p_sws + (size_t)l*256*XROW, N_ENT, 1, DIM,
                nullptr, 0, p_agg, p_dinv, bias + (size_t)l*DIM, xout[l]);
            xin = xout[l];
        }
        k_dense<<<dim3(MTILES, 5), 256>>>(
            p_xs2, p_gws, N_ENT, 0, D3, p_xW, D3, nullptr, nullptr, nullptr, nullptr);
        k_dense<<<dim3(MTILES, 5), 256>>>(
            p_hs, p_gus, N_ENT, 0, D3, p_hU, D3, nullptr, nullptr, nullptr, nullptr);
        k_gru<<<(N_ENT*DIM + 255)/256, 256>>>(b_gates);
    }

    k_score<<<NQ/32, 256>>>(triples, rel_emb, fc1, fc1_b, fc2, fc2_b, out);
}

// round 7
// speedup vs baseline: 1.8439x; 1.1208x over previous
#include <cuda_runtime.h>
#include <cuda_fp16.h>
#include <math.h>
#include <stdint.h>

#define N_ENT 20000
#define DIM   200
#define RR    20
#define NB    20
#define NL    2
#define NT    2
#define NE    250000
#define NQ    8192
#define HID   256
#define D3    600

#define BM 128
#define EGRID 1973
#define EPADTOT (EGRID*BM)
#define MTILES 157
#define GNPAD 640
#define XROW 512              // halves per row: 256 hi + 256 lo
#define NSLAB 7               // 7*32 = 224 >= 200

#define XS 64.0f
#define WS 2048.0f
#define SCALE_INV (1.0f/131072.0f)

// dynamic smem layout (bytes): A[2 stages][2 parts][128 rows][80], B same, idx
#define STG_STRIDE 20480
#define PART_STRIDE 10240
#define OFF_B 40960
#define OFF_SRC 81920
#define OFF_RCV 82432
#define P_SMEM 82944

// ---------------- device scratch ----------------
__device__ __align__(16) float g_relw[NL*RR*DIM*DIM];
__device__ __align__(16) float g_h  [N_ENT*DIM];
__device__ __align__(16) float g_agg[N_ENT*DIM];
__device__ __align__(16) float g_xW [N_ENT*D3];
__device__ __align__(16) float g_hU [N_ENT*D3];
__device__ float g_deg[N_ENT];
__device__ float g_deginv[N_ENT];
__device__ int   g_perm[EPADTOT];
__device__ int   g_cnt[RR];
__device__ int   g_cur[RR];
__device__ __align__(16) __half g_hs [(size_t)N_ENT*XROW];
__device__ __align__(16) __half g_xs1[(size_t)N_ENT*XROW];
__device__ __align__(16) __half g_xs2[(size_t)N_ENT*XROW];
__device__ __align__(16) __half g_ws [(size_t)NL*RR*256*XROW];
__device__ __align__(16) __half g_sws[(size_t)NL*256*XROW];
__device__ __align__(16) __half g_gws[(size_t)GNPAD*XROW];
__device__ __align__(16) __half g_gus[(size_t)GNPAD*XROW];

// ---------------- helpers ----------------
__device__ __forceinline__ uint32_t smem_u32(const void* p) {
    uint32_t a;
    asm("{ .reg .u64 t; cvta.to.shared.u64 t, %1; cvt.u32.u64 %0, t; }" : "=r"(a) : "l"(p));
    return a;
}
__device__ __forceinline__ void mma16(float* c, const uint32_t* a, uint32_t b0, uint32_t b1) {
    asm volatile(
        "mma.sync.aligned.m16n8k16.row.col.f32.f16.f16.f32 "
        "{%0,%1,%2,%3}, {%4,%5,%6,%7}, {%8,%9}, {%0,%1,%2,%3};"
        : "+f"(c[0]), "+f"(c[1]), "+f"(c[2]), "+f"(c[3])
        : "r"(a[0]), "r"(a[1]), "r"(a[2]), "r"(a[3]), "r"(b0), "r"(b1));
}
__device__ __forceinline__ void ldx4(uint32_t* r, uint32_t addr) {
    asm volatile("ldmatrix.sync.aligned.m8n8.x4.shared.b16 {%0,%1,%2,%3}, [%4];"
        : "=r"(r[0]), "=r"(r[1]), "=r"(r[2]), "=r"(r[3]) : "r"(addr));
}
__device__ __forceinline__ void cpa16(uint32_t dst, const void* src) {
    asm volatile("cp.async.cg.shared.global [%0], [%1], 16;" :: "r"(dst), "l"(src) : "memory");
}
__device__ __forceinline__ void cpa_commit() {
    asm volatile("cp.async.commit_group;" ::: "memory");
}
__device__ __forceinline__ void cpa_wait1() {
    asm volatile("cp.async.wait_group 1;" ::: "memory");
}
__device__ __forceinline__ void cpa_wait0() {
    asm volatile("cp.async.wait_group 0;" ::: "memory");
}
__device__ __forceinline__ void red2(float* p, float a, float b) {
    asm volatile("red.global.add.v2.f32 [%0], {%1,%2};"
                 :: "l"(p), "f"(a), "f"(b) : "memory");
}
__device__ __forceinline__ float sigf(float x) { return 1.f / (1.f + expf(-x)); }

// one k32 slab of 3-pass fp16 mma on stage st
__device__ __forceinline__ void slab_mma(uint32_t sb, int st, int wm, int wn, int lane,
                                         float (*acc)[4][4]) {
    uint32_t abase = sb + st*STG_STRIDE;
    uint32_t bbase = sb + OFF_B + st*STG_STRIDE;
    int rowoff = (lane & 15)*80 + ((lane >> 4)*16);
#pragma unroll
    for (int kk = 0; kk < 2; ++kk) {
        uint32_t aH[2][4], aL[2][4], bH[2][4], bL[2][4];
#pragma unroll
        for (int mi = 0; mi < 2; ++mi) {
            uint32_t ra = abase + (wm + mi*16)*80 + rowoff + kk*32;
            ldx4(aH[mi], ra);
            ldx4(aL[mi], ra + PART_STRIDE);
        }
#pragma unroll
        for (int nj2 = 0; nj2 < 2; ++nj2) {
            uint32_t rb = bbase + (wn + nj2*16)*80 + rowoff + kk*32;
            ldx4(bH[nj2], rb);
            ldx4(bL[nj2], rb + PART_STRIDE);
        }
        // x4 on a 16(n)x16(k) tile returns: reg0=(n0-7,k0-7) reg1=(n8-15,k0-7)
        //                                   reg2=(n0-7,k8-15) reg3=(n8-15,k8-15)
        // so n-block (nj&1): b0 = reg[nj&1], b1 = reg[(nj&1)+2]
#pragma unroll
        for (int mi = 0; mi < 2; ++mi)
#pragma unroll
            for (int nj = 0; nj < 4; ++nj) {
                uint32_t b0h = bH[nj>>1][nj&1], b1h = bH[nj>>1][(nj&1)+2];
                uint32_t b0l = bL[nj>>1][nj&1], b1l = bL[nj>>1][(nj&1)+2];
                mma16(acc[mi][nj], aH[mi], b0h, b1h);
                mma16(acc[mi][nj], aL[mi], b0h, b1h);
                mma16(acc[mi][nj], aH[mi], b0l, b1l);
            }
    }
}

// ---------------- small utility kernels ----------------
__global__ void k_zerof(float* p, int n) {
    int i = blockIdx.x*blockDim.x + threadIdx.x;
    for (; i < n; i += gridDim.x*blockDim.x) p[i] = 0.f;
}
__global__ void k_filli(int* p, int n, int v) {
    int i = blockIdx.x*blockDim.x + threadIdx.x;
    for (; i < n; i += gridDim.x*blockDim.x) p[i] = v;
}
__global__ void k_copy(float* dst, const float* src, int n) {
    int i = blockIdx.x*blockDim.x + threadIdx.x;
    for (; i < n; i += gridDim.x*blockDim.x) dst[i] = src[i];
}

__global__ void k_relw(const float* __restrict__ basis, const float* __restrict__ coeff) {
    __shared__ float s_co[NL*RR*NB];
    int tid = threadIdx.x;
    for (int i = tid; i < NL*RR*NB; i += blockDim.x) s_co[i] = coeff[i];
    __syncthreads();
    int gid = blockIdx.x*blockDim.x + tid;
    if (gid >= NL*DIM*DIM) return;
    int l = gid / (DIM*DIM);
    int rem = gid % (DIM*DIM);
    int i = rem / DIM, o = rem % DIM;
    float acc[RR];
#pragma unroll
    for (int r = 0; r < RR; ++r) acc[r] = 0.f;
    for (int b = 0; b < NB; ++b) {
        float bv = basis[((l*NB + b)*DIM + i)*DIM + o];
#pragma unroll
        for (int r = 0; r < RR; ++r) acc[r] += s_co[(l*RR + r)*NB + b] * bv;
    }
    for (int r = 0; r < RR; ++r)
        g_relw[((l*RR + r)*DIM + i)*DIM + o] = acc[r];
}

__global__ void k_splitw(const float* __restrict__ src, __half* __restrict__ dst,
                         int Nsrc, int Nvalid, size_t sstride, size_t dstride) {
    int b = blockIdx.z;
    int idx = blockIdx.x*blockDim.x + threadIdx.x;
    int n = idx >> 8, k = idx & 255;
    float v = 0.f;
    if (n < Nvalid && k < DIM) v = src[b*sstride + (size_t)k*Nsrc + n] * WS;
    __half hi = __float2half_rn(v);
    float lo = v - __half2float(hi);
    dst[b*dstride + (size_t)n*XROW + k]       = hi;
    dst[b*dstride + (size_t)n*XROW + 256 + k] = __float2half_rn(lo);
}

__global__ void k_splitx(const float* __restrict__ src, __half* __restrict__ dst) {
    int idx = blockIdx.x*blockDim.x + threadIdx.x;
    if (idx >= N_ENT*256) return;
    int n = idx >> 8, c = idx & 255;
    float v = (c < DIM) ? src[(size_t)n*DIM + c] * XS : 0.f;
    __half hi = __float2half_rn(v);
    float lo = v - __half2float(hi);
    dst[(size_t)n*XROW + c]       = hi;
    dst[(size_t)n*XROW + 256 + c] = __float2half_rn(lo);
}

__global__ void k_deg_acc(const int* __restrict__ rcv) {
    int i = blockIdx.x*blockDim.x + threadIdx.x;
    for (; i < NE; i += gridDim.x*blockDim.x) atomicAdd(&g_deg[rcv[i]], 1.f);
}
__global__ void k_deginv() {
    int i = blockIdx.x*blockDim.x + threadIdx.x;
    if (i < N_ENT) g_deginv[i] = 1.f / fmaxf(g_deg[i], 1.f);
}
__global__ void k_hist(const int* __restrict__ rel) {
    __shared__ int s_cnt[RR];
    int tid = threadIdx.x;
    if (tid < RR) s_cnt[tid] = 0;
    __syncthreads();
    int i = blockIdx.x*blockDim.x + tid;
    for (; i < NE; i += gridDim.x*blockDim.x) atomicAdd(&s_cnt[rel[i]], 1);
    __syncthreads();
    if (tid < RR) atomicAdd(&g_cnt[tid], s_cnt[tid]);
}
__global__ void k_scan() {
    int run = 0;
    for (int r = 0; r < RR; ++r) {
        g_cur[r] = run;
        run += ((g_cnt[r] + BM - 1) / BM) * BM;
    }
}
__global__ void k_scatter(const int* __restrict__ rel) {
    int i = blockIdx.x*blockDim.x + threadIdx.x;
    for (; i < NE; i += gridDim.x*blockDim.x) {
        int r = rel[i];
        int p = atomicAdd(&g_cur[r], 1);
        g_perm[p] = i;
    }
}

// ---------------- edge gather-GEMM-scatter ----------------
__global__ void __launch_bounds__(512)
k_edge(const __half* __restrict__ xs, const __half* __restrict__ wsl,
       const int* __restrict__ snd, const int* __restrict__ rcv,
       const int* __restrict__ relt) {
    extern __shared__ __align__(16) char sm[];
    uint32_t sb = smem_u32(sm);
    int* s_src = (int*)(sm + OFF_SRC);
    int* s_rcv = (int*)(sm + OFF_RCV);
    int tid = threadIdx.x, lane = tid & 31, w = tid >> 5;

    int e0 = g_perm[blockIdx.x*BM];
    if (e0 < 0) return;
    int rel = relt[e0];
    if (tid < BM) {
        int e = g_perm[blockIdx.x*BM + tid];
        int sv = 0, rv = -1;
        if (e >= 0) { sv = snd[e]; rv = rcv[e]; }
        s_src[tid] = sv; s_rcv[tid] = rv;
    }
    __syncthreads();

    const __half* wr = wsl + (size_t)rel * (256*XROW);
    int n0 = blockIdx.y * BM;
    int wm = (w & 3)*32, wn = (w >> 2)*32;
    int grp = lane >> 2, qid = lane & 3;

    float acc[2][4][4];
#pragma unroll
    for (int a = 0; a < 2; ++a)
#pragma unroll
        for (int b = 0; b < 4; ++b)
#pragma unroll
            for (int c = 0; c < 4; ++c) acc[a][b][c] = 0.f;

#define E_ISSUE(s, st)                                                           \
    {                                                                            \
        for (int j = tid; j < 2048; j += 512) {                                  \
            int op = j >> 10, rem = j & 1023, part = rem >> 9, q = rem & 511;    \
            int row = q >> 2, ch = q & 3;                                        \
            if (op == 0) {                                                       \
                cpa16(sb + (st)*STG_STRIDE + part*PART_STRIDE + row*80 + ch*16,  \
                      xs + (size_t)s_src[row]*XROW + part*256 + (s)*32 + ch*8);  \
            } else {                                                             \
                cpa16(sb + OFF_B + (st)*STG_STRIDE + part*PART_STRIDE + row*80 + ch*16, \
                      wr + (size_t)(n0 + row)*XROW + part*256 + (s)*32 + ch*8);  \
            }                                                                    \
        }                                                                        \
        cpa_commit();                                                            \
    }

    E_ISSUE(0, 0);
    for (int s = 0; s < NSLAB; ++s) {
        if (s + 1 < NSLAB) { E_ISSUE(s + 1, (s + 1) & 1); cpa_wait1(); }
        else cpa_wait0();
        __syncthreads();
        slab_mma(sb, s & 1, wm, wn, lane, acc);
        __syncthreads();
    }
#undef E_ISSUE

#pragma unroll
    for (int mi = 0; mi < 2; ++mi) {
        int r0 = wm + mi*16 + grp;
        int rv0 = s_rcv[r0], rv1 = s_rcv[r0 + 8];
#pragma unroll
        for (int nj = 0; nj < 4; ++nj) {
            int col = n0 + wn + nj*8 + qid*2;
            if (col >= DIM) continue;
            float* c = acc[mi][nj];
            if (rv0 >= 0) red2(g_agg + (size_t)rv0*DIM + col, c[0]*SCALE_INV, c[1]*SCALE_INV);
            if (rv1 >= 0) red2(g_agg + (size_t)rv1*DIM + col, c[2]*SCALE_INV, c[3]*SCALE_INV);
        }
    }
}

// ---------------- dense GEMM ----------------
__global__ void __launch_bounds__(512)
k_dense(const __half* __restrict__ Axs, const __half* __restrict__ Bws,
        int M, int mode, int Nvalid,
        float* __restrict__ C, int ldC,
        const float* __restrict__ agg, const float* __restrict__ dinv,
        const float* __restrict__ bias, __half* __restrict__ out_xs) {
    extern __shared__ __align__(16) char sm[];
    uint32_t sb = smem_u32(sm);
    int tid = threadIdx.x, lane = tid & 31, w = tid >> 5;
    int m0 = blockIdx.x * BM;
    int n0 = blockIdx.y * BM;
    int wm = (w & 3)*32, wn = (w >> 2)*32;
    int grp = lane >> 2, qid = lane & 3;

    float acc[2][4][4];
#pragma unroll
    for (int a = 0; a < 2; ++a)
#pragma unroll
        for (int b = 0; b < 4; ++b)
#pragma unroll
            for (int c = 0; c < 4; ++c) acc[a][b][c] = 0.f;

#define D_ISSUE(s, st)                                                           \
    {                                                                            \
        for (int j = tid; j < 2048; j += 512) {                                  \
            int op = j >> 10, rem = j & 1023, part = rem >> 9, q = rem & 511;    \
            int row = q >> 2, ch = q & 3;                                        \
            if (op == 0) {                                                       \
                int gm = m0 + row; if (gm >= M) gm = 0;                          \
                cpa16(sb + (st)*STG_STRIDE + part*PART_STRIDE + row*80 + ch*16,  \
                      Axs + (size_t)gm*XROW + part*256 + (s)*32 + ch*8);         \
            } else {                                                             \
                cpa16(sb + OFF_B + (st)*STG_STRIDE + part*PART_STRIDE + row*80 + ch*16, \
                      Bws + (size_t)(n0 + row)*XROW + part*256 + (s)*32 + ch*8); \
            }                                                                    \
        }                                                                        \
        cpa_commit();                                                            \
    }

    D_ISSUE(0, 0);
    for (int s = 0; s < NSLAB; ++s) {
        if (s + 1 < NSLAB) { D_ISSUE(s + 1, (s + 1) & 1); cpa_wait1(); }
        else cpa_wait0();
        __syncthreads();
        slab_mma(sb, s & 1, wm, wn, lane, acc);
        __syncthreads();
    }
#undef D_ISSUE

#pragma unroll
    for (int mi = 0; mi < 2; ++mi) {
        int r0 = m0 + wm + mi*16 + grp;
        int r1 = r0 + 8;
#pragma unroll
        for (int nj = 0; nj < 4; ++nj) {
            int col = n0 + wn + nj*8 + qid*2;
            float* c = acc[mi][nj];
            if (mode == 0) {
                if (col >= Nvalid) continue;
                if (r0 < M) *(float2*)(C + (size_t)r0*ldC + col) =
                    make_float2(c[0]*SCALE_INV, c[1]*SCALE_INV);
                if (r1 < M) *(float2*)(C + (size_t)r1*ldC + col) =
                    make_float2(c[2]*SCALE_INV, c[3]*SCALE_INV);
            } else {
#pragma unroll
                for (int h = 0; h < 2; ++h) {
                    int row = h ? r1 : r0;
                    if (row >= M) continue;
                    float v0 = 0.f, v1 = 0.f;
                    if (col < DIM) {
                        float dv = dinv[row];
                        float a0 = agg[(size_t)row*DIM + col]*dv + bias[col];
                        float a1 = agg[(size_t)row*DIM + col + 1]*dv + bias[col + 1];
                        v0 = fmaxf(c[h*2+0]*SCALE_INV + a0, 0.f) * XS;
                        v1 = fmaxf(c[h*2+1]*SCALE_INV + a1, 0.f) * XS;
                    }
                    __half h0 = __float2half_rn(v0), h1 = __float2half_rn(v1);
                    float l0 = v0 - __half2float(h0), l1 = v1 - __half2float(h1);
                    *(__half2*)(out_xs + (size_t)row*XROW + col) = __halves2half2(h0, h1);
                    *(__half2*)(out_xs + (size_t)row*XROW + 256 + col) =
                        __halves2half2(__float2half_rn(l0), __float2half_rn(l1));
                }
            }
        }
    }
}

__global__ void k_gru(const float* __restrict__ bg) {
    int idx = blockIdx.x*blockDim.x + threadIdx.x;
    if (idx >= N_ENT*DIM) return;
    int n = idx / DIM, c = idx % DIM;
    size_t b = (size_t)n*D3;
    float r  = sigf(g_xW[b + c]        + g_hU[b + c]        + bg[c]);
    float z  = sigf(g_xW[b + DIM + c]  + g_hU[b + DIM + c]  + bg[DIM + c]);
    float hu3 = g_hU[b + 2*DIM + c];
    float ht = tanhf(g_xW[b + 2*DIM + c] + hu3 + bg[2*DIM + c] + r * hu3);
    float h0 = g_h[idx];
    float hn = (1.f - z)*h0 + z*ht;
    g_h[idx] = hn;
    float X = hn * XS;
    __half hi = __float2half_rn(X);
    float lo = X - __half2float(hi);
    g_hs[(size_t)n*XROW + c]       = hi;
    g_hs[(size_t)n*XROW + 256 + c] = __float2half_rn(lo);
}

__global__ void __launch_bounds__(256)
k_score(const int* __restrict__ triples, const float* __restrict__ rel_emb,
        const float* __restrict__ fc1, const float* __restrict__ b1,
        const float* __restrict__ fc2, const float* __restrict__ fc2b,
        float* __restrict__ out) {
    __shared__ float As[32][8];
    __shared__ float Bs[8][HID];
    __shared__ int s_s[32], s_r[32], s_o[32];
    int tid = threadIdx.x;
    int qbase = blockIdx.x * 32;
    if (tid < 32) {
        s_s[tid] = triples[(qbase + tid)*3 + 0];
        s_r[tid] = triples[(qbase + tid)*3 + 1];
        s_o[tid] = triples[(qbase + tid)*3 + 2];
    }
    __syncthreads();
    int w = tid >> 5, lane = tid & 31;
    float acc[4][8];
#pragma unroll
    for (int i = 0; i < 4; ++i)
#pragma unroll
        for (int j = 0; j < 8; ++j) acc[i][j] = 0.f;

    for (int k0 = 0; k0 < D3; k0 += 8) {
        {
            int qi = tid >> 3, kk = tid & 7, k = k0 + kk;
            float v;
            if (k < DIM)            v = g_h[(size_t)s_s[qi]*DIM + k];
            else if (k < 2*DIM)     v = rel_emb[(size_t)s_r[qi]*DIM + (k - DIM)];
            else                    v = g_h[(size_t)s_o[qi]*DIM + (k - 2*DIM)];
            As[qi][kk] = v;
        }
        {
            int kr = tid >> 5, cb = tid & 31;
#pragma unroll
            for (int j = 0; j < 8; ++j)
                Bs[kr][cb + 32*j] = fc1[(size_t)(k0 + kr)*HID + cb + 32*j];
        }
        __syncthreads();
#pragma unroll
        for (int kk = 0; kk < 8; ++kk) {
#pragma unroll
            for (int i = 0; i < 4; ++i) {
                float a = As[w*4 + i][kk];
#pragma unroll
                for (int j = 0; j < 8; ++j)
                    acc[i][j] += a * Bs[kk][lane + 32*j];
            }
        }
        __syncthreads();
    }
#pragma unroll
    for (int i = 0; i < 4; ++i) {
        float p = 0.f;
#pragma unroll
        for (int j = 0; j < 8; ++j) {
            int col = lane + 32*j;
            float hv = fmaxf(acc[i][j] + b1[col], 0.f);
            p += hv * fc2[col];
        }
#pragma unroll
        for (int off = 16; off > 0; off >>= 1)
            p += __shfl_down_sync(0xffffffffu, p, off);
        if (lane == 0) out[qbase + w*4 + i] = p + fc2b[0];
    }
}

// ---------------- host ----------------
extern "C" void kernel_launch(void* const* d_in, const int* in_sizes, int n_in,
                              void* d_out, int out_size) {
    const float* entity_emb = (const float*)d_in[0];
    const float* basis      = (const float*)d_in[1];
    const float* coeff      = (const float*)d_in[2];
    const float* self_w     = (const float*)d_in[3];
    const float* bias       = (const float*)d_in[4];
    const float* W_gates    = (const float*)d_in[5];
    const float* U_gates    = (const float*)d_in[6];
    const float* b_gates    = (const float*)d_in[7];
    const float* rel_emb    = (const float*)d_in[8];
    const float* fc1        = (const float*)d_in[9];
    const float* fc1_b      = (const float*)d_in[10];
    const float* fc2        = (const float*)d_in[11];
    const float* fc2_b      = (const float*)d_in[12];
    const int*   senders    = (const int*)d_in[13];
    const int*   receivers  = (const int*)d_in[14];
    const int*   rel_types  = (const int*)d_in[15];
    const int*   triples    = (const int*)d_in[16];
    float* out = (float*)d_out;

    cudaFuncSetAttribute(k_edge,  cudaFuncAttributeMaxDynamicSharedMemorySize, P_SMEM);
    cudaFuncSetAttribute(k_dense, cudaFuncAttributeMaxDynamicSharedMemorySize, P_SMEM);

    float *p_relw, *p_h, *p_agg, *p_deg, *p_dinv, *p_xW, *p_hU;
    int *p_perm, *p_cnt;
    __half *p_hs, *p_xs1, *p_xs2, *p_ws, *p_sws, *p_gws, *p_gus;
    cudaGetSymbolAddress((void**)&p_relw, g_relw);
    cudaGetSymbolAddress((void**)&p_h,    g_h);
    cudaGetSymbolAddress((void**)&p_agg,  g_agg);
    cudaGetSymbolAddress((void**)&p_deg,  g_deg);
    cudaGetSymbolAddress((void**)&p_dinv, g_deginv);
    cudaGetSymbolAddress((void**)&p_perm, g_perm);
    cudaGetSymbolAddress((void**)&p_cnt,  g_cnt);
    cudaGetSymbolAddress((void**)&p_xW,   g_xW);
    cudaGetSymbolAddress((void**)&p_hU,   g_hU);
    cudaGetSymbolAddress((void**)&p_hs,   g_hs);
    cudaGetSymbolAddress((void**)&p_xs1,  g_xs1);
    cudaGetSymbolAddress((void**)&p_xs2,  g_xs2);
    cudaGetSymbolAddress((void**)&p_ws,   g_ws);
    cudaGetSymbolAddress((void**)&p_sws,  g_sws);
    cudaGetSymbolAddress((void**)&p_gws,  g_gws);
    cudaGetSymbolAddress((void**)&p_gus,  g_gus);

    k_relw<<<(NL*DIM*DIM + 255)/256, 256>>>(basis, coeff);
    k_splitw<<<dim3(256, 1, NL*RR), 256>>>(p_relw, p_ws, DIM, DIM,
                                           (size_t)DIM*DIM, (size_t)256*XROW);
    k_splitw<<<dim3(256, 1, NL), 256>>>(self_w, p_sws, DIM, DIM,
                                        (size_t)DIM*DIM, (size_t)256*XROW);
    k_splitw<<<dim3(GNPAD, 1, 1), 256>>>(W_gates, p_gws, D3, D3, 0, 0);
    k_splitw<<<dim3(GNPAD, 1, 1), 256>>>(U_gates, p_gus, D3, D3, 0, 0);
    k_splitx<<<(N_ENT*256 + 255)/256, 256>>>(entity_emb, p_hs);
    k_copy<<<1024, 256>>>(p_h, entity_emb, N_ENT*DIM);

    for (int t = 0; t < NT; ++t) {
        const int* snd = senders   + (size_t)t*NE;
        const int* rcv = receivers + (size_t)t*NE;
        const int* rlt = rel_types + (size_t)t*NE;

        k_zerof<<<256, 256>>>(p_deg, N_ENT);
        k_deg_acc<<<512, 256>>>(rcv);
        k_deginv<<<(N_ENT + 255)/256, 256>>>();

        k_filli<<<512, 256>>>(p_perm, EPADTOT, -1);
        k_filli<<<1, 32>>>(p_cnt, RR, 0);
        k_hist<<<256, 256>>>(rlt);
        k_scan<<<1, 1>>>();
        k_scatter<<<512, 256>>>(rlt);

        const __half* xin = p_hs;
        __half* xout[2] = { p_xs1, p_xs2 };
        for (int l = 0; l < NL; ++l) {
            k_zerof<<<1024, 256>>>(p_agg, N_ENT*DIM);
            k_edge<<<dim3(EGRID, 2), 512, P_SMEM>>>(xin, p_ws + (size_t)l*RR*256*XROW,
                                                    snd, rcv, rlt);
            k_dense<<<dim3(MTILES, 2), 512, P_SMEM>>>(
                xin, p_sws + (size_t)l*256*XROW, N_ENT, 1, DIM,
                nullptr, 0, p_agg, p_dinv, bias + (size_t)l*DIM, xout[l]);
            xin = xout[l];
        }
        k_dense<<<dim3(MTILES, 5), 512, P_SMEM>>>(
            p_xs2, p_gws, N_ENT, 0, D3, p_xW, D3, nullptr, nullptr, nullptr, nullptr);
        k_dense<<<dim3(MTILES, 5), 512, P_SMEM>>>(
            p_hs, p_gus, N_ENT, 0, D3, p_hU, D3, nullptr, nullptr, nullptr, nullptr);
        k_gru<<<(N_ENT*DIM + 255)/256, 256>>>(b_gates);
    }

    k_score<<<NQ/32, 256>>>(triples, rel_emb, fc1, fc1_b, fc2, fc2_b, out);
}

// round 8
// speedup vs baseline: 2.0977x; 1.1377x over previous
#include <cuda_runtime.h>
#include <cuda_fp16.h>
#include <math.h>
#include <stdint.h>

#define N_ENT 20000
#define DIM   200
#define RR    20
#define NB    20
#define NL    2
#define NT    2
#define NE    250000
#define NQ    8192
#define HID   256
#define D3    600

#define BM 128
#define EGRID 1973
#define EPADTOT (EGRID*BM)
#define MTILES 157
#define GNPAD 640
#define XROW 512              // halves per row: 256 hi + 256 lo
#define NSLAB 7               // 7*32 = 224 >= 200

#define XS 64.0f
#define WS 2048.0f
#define SCALE_INV (1.0f/131072.0f)

// dynamic smem (bytes): A[2 stages][2 parts][128 rows][80], B[2 stages][1 part][128][80]
#define A_STG 20480
#define PART_STRIDE 10240
#define OFF_B 40960
#define B_STG 10240
#define OFF_SRC 61440
#define OFF_RCV 61952
#define P_SMEM 62464

// ---------------- device scratch ----------------
__device__ __align__(16) float g_relw[NL*RR*DIM*DIM];
__device__ __align__(16) float g_h  [N_ENT*DIM];
__device__ __align__(16) float g_agg[N_ENT*DIM];
__device__ __align__(16) float g_xW [N_ENT*D3];
__device__ __align__(16) float g_hU [N_ENT*D3];
__device__ float g_deg[N_ENT];
__device__ float g_deginv[N_ENT];
__device__ int   g_perm[EPADTOT];
__device__ int   g_cnt[RR];
__device__ int   g_cur[RR];
__device__ __align__(16) __half g_hs [(size_t)N_ENT*XROW];
__device__ __align__(16) __half g_xs1[(size_t)N_ENT*XROW];
__device__ __align__(16) __half g_xs2[(size_t)N_ENT*XROW];
__device__ __align__(16) __half g_ws [(size_t)NL*RR*256*XROW];
__device__ __align__(16) __half g_sws[(size_t)NL*256*XROW];
__device__ __align__(16) __half g_gws[(size_t)GNPAD*XROW];
__device__ __align__(16) __half g_gus[(size_t)GNPAD*XROW];

// ---------------- helpers ----------------
__device__ __forceinline__ uint32_t smem_u32(const void* p) {
    uint32_t a;
    asm("{ .reg .u64 t; cvta.to.shared.u64 t, %1; cvt.u32.u64 %0, t; }" : "=r"(a) : "l"(p));
    return a;
}
__device__ __forceinline__ void mma16(float* c, const uint32_t* a, uint32_t b0, uint32_t b1) {
    asm volatile(
        "mma.sync.aligned.m16n8k16.row.col.f32.f16.f16.f32 "
        "{%0,%1,%2,%3}, {%4,%5,%6,%7}, {%8,%9}, {%0,%1,%2,%3};"
        : "+f"(c[0]), "+f"(c[1]), "+f"(c[2]), "+f"(c[3])
        : "r"(a[0]), "r"(a[1]), "r"(a[2]), "r"(a[3]), "r"(b0), "r"(b1));
}
__device__ __forceinline__ void ldx4(uint32_t* r, uint32_t addr) {
    asm volatile("ldmatrix.sync.aligned.m8n8.x4.shared.b16 {%0,%1,%2,%3}, [%4];"
        : "=r"(r[0]), "=r"(r[1]), "=r"(r[2]), "=r"(r[3]) : "r"(addr));
}
__device__ __forceinline__ void cpa16(uint32_t dst, const void* src) {
    asm volatile("cp.async.cg.shared.global [%0], [%1], 16;" :: "r"(dst), "l"(src) : "memory");
}
__device__ __forceinline__ void cpa_commit() {
    asm volatile("cp.async.commit_group;" ::: "memory");
}
__device__ __forceinline__ void cpa_wait1() {
    asm volatile("cp.async.wait_group 1;" ::: "memory");
}
__device__ __forceinline__ void cpa_wait0() {
    asm volatile("cp.async.wait_group 0;" ::: "memory");
}
__device__ __forceinline__ void red2(float* p, float a, float b) {
    asm volatile("red.global.add.v2.f32 [%0], {%1,%2};"
                 :: "l"(p), "f"(a), "f"(b) : "memory");
}
__device__ __forceinline__ float sigf(float x) { return 1.f / (1.f + expf(-x)); }

// one k32 slab of 2-pass fp16 mma on stage st (C = A*Bhi exactly: AhBh + AlBh)
// nlim: local column-validity limit within the 128-wide tile (skip dead n-blocks)
__device__ __forceinline__ void slab_mma(uint32_t sb, int st, int wm, int wn, int lane,
                                         int nlim, float (*acc)[4][4]) {
    uint32_t abase = sb + st*A_STG;
    uint32_t bbase = sb + OFF_B + st*B_STG;
    int rowoff = (lane & 15)*80 + ((lane >> 4)*16);
#pragma unroll
    for (int kk = 0; kk < 2; ++kk) {
        uint32_t aH[2][4], aL[2][4], bH[2][4];
#pragma unroll
        for (int mi = 0; mi < 2; ++mi) {
            uint32_t ra = abase + (wm + mi*16)*80 + rowoff + kk*32;
            ldx4(aH[mi], ra);
            ldx4(aL[mi], ra + PART_STRIDE);
        }
#pragma unroll
        for (int nj2 = 0; nj2 < 2; ++nj2) {
            if (wn + nj2*16 < nlim) {
                uint32_t rb = bbase + (wn + nj2*16)*80 + rowoff + kk*32;
                ldx4(bH[nj2], rb);
            }
        }
        // x4 on 16(n)x16(k): reg0=(n0-7,k0-7) reg1=(n8-15,k0-7) reg2=(n0-7,k8-15) reg3=(n8-15,k8-15)
#pragma unroll
        for (int mi = 0; mi < 2; ++mi)
#pragma unroll
            for (int nj = 0; nj < 4; ++nj) {
                if (wn + nj*8 >= nlim) continue;
                uint32_t b0 = bH[nj>>1][nj&1], b1 = bH[nj>>1][(nj&1)+2];
                mma16(acc[mi][nj], aH[mi], b0, b1);
                mma16(acc[mi][nj], aL[mi], b0, b1);
            }
    }
}

// ---------------- small utility kernels ----------------
__global__ void k_zerof(float* p, int n) {
    int i = blockIdx.x*blockDim.x + threadIdx.x;
    for (; i < n; i += gridDim.x*blockDim.x) p[i] = 0.f;
}
__global__ void k_filli(int* p, int n, int v) {
    int i = blockIdx.x*blockDim.x + threadIdx.x;
    for (; i < n; i += gridDim.x*blockDim.x) p[i] = v;
}
__global__ void k_copy(float* dst, const float* src, int n) {
    int i = blockIdx.x*blockDim.x + threadIdx.x;
    for (; i < n; i += gridDim.x*blockDim.x) dst[i] = src[i];
}

__global__ void k_relw(const float* __restrict__ basis, const float* __restrict__ coeff) {
    __shared__ float s_co[NL*RR*NB];
    int tid = threadIdx.x;
    for (int i = tid; i < NL*RR*NB; i += blockDim.x) s_co[i] = coeff[i];
    __syncthreads();
    int gid = blockIdx.x*blockDim.x + tid;
    if (gid >= NL*DIM*DIM) return;
    int l = gid / (DIM*DIM);
    int rem = gid % (DIM*DIM);
    int i = rem / DIM, o = rem % DIM;
    float acc[RR];
#pragma unroll
    for (int r = 0; r < RR; ++r) acc[r] = 0.f;
    for (int b = 0; b < NB; ++b) {
        float bv = basis[((l*NB + b)*DIM + i)*DIM + o];
#pragma unroll
        for (int r = 0; r < RR; ++r) acc[r] += s_co[(l*RR + r)*NB + b] * bv;
    }
    for (int r = 0; r < RR; ++r)
        g_relw[((l*RR + r)*DIM + i)*DIM + o] = acc[r];
}

__global__ void k_splitw(const float* __restrict__ src, __half* __restrict__ dst,
                         int Nsrc, int Nvalid, size_t sstride, size_t dstride) {
    int b = blockIdx.z;
    int idx = blockIdx.x*blockDim.x + threadIdx.x;
    int n = idx >> 8, k = idx & 255;
    float v = 0.f;
    if (n < Nvalid && k < DIM) v = src[b*sstride + (size_t)k*Nsrc + n] * WS;
    __half hi = __float2half_rn(v);
    float lo = v - __half2float(hi);
    dst[b*dstride + (size_t)n*XROW + k]       = hi;
    dst[b*dstride + (size_t)n*XROW + 256 + k] = __float2half_rn(lo);
}

__global__ void k_splitx(const float* __restrict__ src, __half* __restrict__ dst) {
    int idx = blockIdx.x*blockDim.x + threadIdx.x;
    if (idx >= N_ENT*256) return;
    int n = idx >> 8, c = idx & 255;
    float v = (c < DIM) ? src[(size_t)n*DIM + c] * XS : 0.f;
    __half hi = __float2half_rn(v);
    float lo = v - __half2float(hi);
    dst[(size_t)n*XROW + c]       = hi;
    dst[(size_t)n*XROW + 256 + c] = __float2half_rn(lo);
}

__global__ void k_deg_acc(const int* __restrict__ rcv) {
    int i = blockIdx.x*blockDim.x + threadIdx.x;
    for (; i < NE; i += gridDim.x*blockDim.x) atomicAdd(&g_deg[rcv[i]], 1.f);
}
__global__ void k_deginv() {
    int i = blockIdx.x*blockDim.x + threadIdx.x;
    if (i < N_ENT) g_deginv[i] = 1.f / fmaxf(g_deg[i], 1.f);
}
__global__ void k_hist(const int* __restrict__ rel) {
    __shared__ int s_cnt[RR];
    int tid = threadIdx.x;
    if (tid < RR) s_cnt[tid] = 0;
    __syncthreads();
    int i = blockIdx.x*blockDim.x + tid;
    for (; i < NE; i += gridDim.x*blockDim.x) atomicAdd(&s_cnt[rel[i]], 1);
    __syncthreads();
    if (tid < RR) atomicAdd(&g_cnt[tid], s_cnt[tid]);
}
__global__ void k_scan() {
    int run = 0;
    for (int r = 0; r < RR; ++r) {
        g_cur[r] = run;
        run += ((g_cnt[r] + BM - 1) / BM) * BM;
    }
}
__global__ void k_scatter(const int* __restrict__ rel) {
    int i = blockIdx.x*blockDim.x + threadIdx.x;
    for (; i < NE; i += gridDim.x*blockDim.x) {
        int r = rel[i];
        int p = atomicAdd(&g_cur[r], 1);
        g_perm[p] = i;
    }
}

// ---------------- edge gather-GEMM-scatter ----------------
__global__ void __launch_bounds__(512)
k_edge(const __half* __restrict__ xs, const __half* __restrict__ wsl,
       const int* __restrict__ snd, const int* __restrict__ rcv,
       const int* __restrict__ relt) {
    extern __shared__ __align__(16) char sm[];
    uint32_t sb = smem_u32(sm);
    int* s_src = (int*)(sm + OFF_SRC);
    int* s_rcv = (int*)(sm + OFF_RCV);
    int tid = threadIdx.x, lane = tid & 31, w = tid >> 5;

    int e0 = g_perm[blockIdx.x*BM];
    if (e0 < 0) return;
    int rel = relt[e0];
    if (tid < BM) {
        int e = g_perm[blockIdx.x*BM + tid];
        int sv = 0, rv = -1;
        if (e >= 0) { sv = snd[e]; rv = rcv[e]; }
        s_src[tid] = sv; s_rcv[tid] = rv;
    }
    __syncthreads();

    const __half* wr = wsl + (size_t)rel * (256*XROW);
    int n0 = blockIdx.y * BM;
    int nlim = DIM - n0; if (nlim > BM) nlim = BM;
    int wm = (w & 3)*32, wn = (w >> 2)*32;
    int grp = lane >> 2, qid = lane & 3;

    float acc[2][4][4];
#pragma unroll
    for (int a = 0; a < 2; ++a)
#pragma unroll
        for (int b = 0; b < 4; ++b)
#pragma unroll
            for (int c = 0; c < 4; ++c) acc[a][b][c] = 0.f;

#define E_ISSUE(s, st)                                                           \
    {                                                                            \
        for (int j = tid; j < 1536; j += 512) {                                  \
            if (j < 1024) {                                                      \
                int part = j >> 9, q = j & 511, row = q >> 2, ch = q & 3;        \
                cpa16(sb + (st)*A_STG + part*PART_STRIDE + row*80 + ch*16,       \
                      xs + (size_t)s_src[row]*XROW + part*256 + (s)*32 + ch*8);  \
            } else {                                                             \
                int q = j - 1024, row = q >> 2, ch = q & 3;                      \
                cpa16(sb + OFF_B + (st)*B_STG + row*80 + ch*16,                  \
                      wr + (size_t)(n0 + row)*XROW + (s)*32 + ch*8);             \
            }                                                                    \
        }                                                                        \
        cpa_commit();                                                            \
    }

    E_ISSUE(0, 0);
    for (int s = 0; s < NSLAB; ++s) {
        if (s + 1 < NSLAB) { E_ISSUE(s + 1, (s + 1) & 1); cpa_wait1(); }
        else cpa_wait0();
        __syncthreads();
        slab_mma(sb, s & 1, wm, wn, lane, nlim, acc);
        __syncthreads();
    }
#undef E_ISSUE

#pragma unroll
    for (int mi = 0; mi < 2; ++mi) {
        int r0 = wm + mi*16 + grp;
        int rv0 = s_rcv[r0], rv1 = s_rcv[r0 + 8];
#pragma unroll
        for (int nj = 0; nj < 4; ++nj) {
            int col = n0 + wn + nj*8 + qid*2;
            if (col >= DIM) continue;
            float* c = acc[mi][nj];
            if (rv0 >= 0) red2(g_agg + (size_t)rv0*DIM + col, c[0]*SCALE_INV, c[1]*SCALE_INV);
            if (rv1 >= 0) red2(g_agg + (size_t)rv1*DIM + col, c[2]*SCALE_INV, c[3]*SCALE_INV);
        }
    }
}

// ---------------- dense GEMM ----------------
__global__ void __launch_bounds__(512)
k_dense(const __half* __restrict__ Axs, const __half* __restrict__ Bws,
        int M, int mode, int Nvalid,
        float* __restrict__ C, int ldC,
        const float* __restrict__ agg, const float* __restrict__ dinv,
        const float* __restrict__ bias, __half* __restrict__ out_xs) {
    extern __shared__ __align__(16) char sm[];
    uint32_t sb = smem_u32(sm);
    int tid = threadIdx.x, lane = tid & 31, w = tid >> 5;
    int m0 = blockIdx.x * BM;
    int n0 = blockIdx.y * BM;
    int nlim = Nvalid - n0; if (nlim > BM) nlim = BM; if (nlim < 0) nlim = 0;
    int wm = (w & 3)*32, wn = (w >> 2)*32;
    int grp = lane >> 2, qid = lane & 3;

    float acc[2][4][4];
#pragma unroll
    for (int a = 0; a < 2; ++a)
#pragma unroll
        for (int b = 0; b < 4; ++b)
#pragma unroll
            for (int c = 0; c < 4; ++c) acc[a][b][c] = 0.f;

#define D_ISSUE(s, st)                                                           \
    {                                                                            \
        for (int j = tid; j < 1536; j += 512) {                                  \
            if (j < 1024) {                                                      \
                int part = j >> 9, q = j & 511, row = q >> 2, ch = q & 3;        \
                int gm = m0 + row; if (gm >= M) gm = 0;                          \
                cpa16(sb + (st)*A_STG + part*PART_STRIDE + row*80 + ch*16,       \
                      Axs + (size_t)gm*XROW + part*256 + (s)*32 + ch*8);         \
            } else {                                                             \
                int q = j - 1024, row = q >> 2, ch = q & 3;                      \
                cpa16(sb + OFF_B + (st)*B_STG + row*80 + ch*16,                  \
                      Bws + (size_t)(n0 + row)*XROW + (s)*32 + ch*8);            \
            }                                                                    \
        }                                                                        \
        cpa_commit();                                                            \
    }

    D_ISSUE(0, 0);
    for (int s = 0; s < NSLAB; ++s) {
        if (s + 1 < NSLAB) { D_ISSUE(s + 1, (s + 1) & 1); cpa_wait1(); }
        else cpa_wait0();
        __syncthreads();
        slab_mma(sb, s & 1, wm, wn, lane, nlim, acc);
        __syncthreads();
    }
#undef D_ISSUE

#pragma unroll
    for (int mi = 0; mi < 2; ++mi) {
        int r0 = m0 + wm + mi*16 + grp;
        int r1 = r0 + 8;
#pragma unroll
        for (int nj = 0; nj < 4; ++nj) {
            if (wn + nj*8 >= nlim) continue;   // dead n-block: pad stays zero-init
            int col = n0 + wn + nj*8 + qid*2;
            float* c = acc[mi][nj];
            if (mode == 0) {
                if (col >= Nvalid) continue;
                if (r0 < M) *(float2*)(C + (size_t)r0*ldC + col) =
                    make_float2(c[0]*SCALE_INV, c[1]*SCALE_INV);
                if (r1 < M) *(float2*)(C + (size_t)r1*ldC + col) =
                    make_float2(c[2]*SCALE_INV, c[3]*SCALE_INV);
            } else {
#pragma unroll
                for (int h = 0; h < 2; ++h) {
                    int row = h ? r1 : r0;
                    if (row >= M) continue;
                    float v0 = 0.f, v1 = 0.f;
                    if (col < DIM) {
                        float dv = dinv[row];
                        float a0 = agg[(size_t)row*DIM + col]*dv + bias[col];
                        float a1 = agg[(size_t)row*DIM + col + 1]*dv + bias[col + 1];
                        v0 = fmaxf(c[h*2+0]*SCALE_INV + a0, 0.f) * XS;
                        v1 = fmaxf(c[h*2+1]*SCALE_INV + a1, 0.f) * XS;
                    }
                    __half h0 = __float2half_rn(v0), h1 = __float2half_rn(v1);
                    float l0 = v0 - __half2float(h0), l1 = v1 - __half2float(h1);
                    *(__half2*)(out_xs + (size_t)row*XROW + col) = __halves2half2(h0, h1);
                    *(__half2*)(out_xs + (size_t)row*XROW + 256 + col) =
                        __halves2half2(__float2half_rn(l0), __float2half_rn(l1));
                }
            }
        }
    }
}

__global__ void k_gru(const float* __restrict__ bg) {
    int idx = blockIdx.x*blockDim.x + threadIdx.x;
    if (idx >= N_ENT*DIM) return;
    int n = idx / DIM, c = idx % DIM;
    size_t b = (size_t)n*D3;
    float r  = sigf(g_xW[b + c]        + g_hU[b + c]        + bg[c]);
    float z  = sigf(g_xW[b + DIM + c]  + g_hU[b + DIM + c]  + bg[DIM + c]);
    float hu3 = g_hU[b + 2*DIM + c];
    float ht = tanhf(g_xW[b + 2*DIM + c] + hu3 + bg[2*DIM + c] + r * hu3);
    float h0 = g_h[idx];
    float hn = (1.f - z)*h0 + z*ht;
    g_h[idx] = hn;
    float X = hn * XS;
    __half hi = __float2half_rn(X);
    float lo = X - __half2float(hi);
    g_hs[(size_t)n*XROW + c]       = hi;
    g_hs[(size_t)n*XROW + 256 + c] = __float2half_rn(lo);
}

__global__ void __launch_bounds__(256)
k_score(const int* __restrict__ triples, const float* __restrict__ rel_emb,
        const float* __restrict__ fc1, const float* __restrict__ b1,
        const float* __restrict__ fc2, const float* __restrict__ fc2b,
        float* __restrict__ out) {
    __shared__ float As[32][8];
    __shared__ float Bs[8][HID];
    __shared__ int s_s[32], s_r[32], s_o[32];
    int tid = threadIdx.x;
    int qbase = blockIdx.x * 32;
    if (tid < 32) {
        s_s[tid] = triples[(qbase + tid)*3 + 0];
        s_r[tid] = triples[(qbase + tid)*3 + 1];
        s_o[tid] = triples[(qbase + tid)*3 + 2];
    }
    __syncthreads();
    int w = tid >> 5, lane = tid & 31;
    float acc[4][8];
#pragma unroll
    for (int i = 0; i < 4; ++i)
#pragma unroll
        for (int j = 0; j < 8; ++j) acc[i][j] = 0.f;

    for (int k0 = 0; k0 < D3; k0 += 8) {
        {
            int qi = tid >> 3, kk = tid & 7, k = k0 + kk;
            float v;
            if (k < DIM)            v = g_h[(size_t)s_s[qi]*DIM + k];
            else if (k < 2*DIM)     v = rel_emb[(size_t)s_r[qi]*DIM + (k - DIM)];
            else                    v = g_h[(size_t)s_o[qi]*DIM + (k - 2*DIM)];
            As[qi][kk] = v;
        }
        {
            int kr = tid >> 5, cb = tid & 31;
#pragma unroll
            for (int j = 0; j < 8; ++j)
                Bs[kr][cb + 32*j] = fc1[(size_t)(k0 + kr)*HID + cb + 32*j];
        }
        __syncthreads();
#pragma unroll
        for (int kk = 0; kk < 8; ++kk) {
#pragma unroll
            for (int i = 0; i < 4; ++i) {
                float a = As[w*4 + i][kk];
#pragma unroll
                for (int j = 0; j < 8; ++j)
                    acc[i][j] += a * Bs[kk][lane + 32*j];
            }
        }
        __syncthreads();
    }
#pragma unroll
    for (int i = 0; i < 4; ++i) {
        float p = 0.f;
#pragma unroll
        for (int j = 0; j < 8; ++j) {
            int col = lane + 32*j;
            float hv = fmaxf(acc[i][j] + b1[col], 0.f);
            p += hv * fc2[col];
        }
#pragma unroll
        for (int off = 16; off > 0; off >>= 1)
            p += __shfl_down_sync(0xffffffffu, p, off);
        if (lane == 0) out[qbase + w*4 + i] = p + fc2b[0];
    }
}

// ---------------- host ----------------
extern "C" void kernel_launch(void* const* d_in, const int* in_sizes, int n_in,
                              void* d_out, int out_size) {
    const float* entity_emb = (const float*)d_in[0];
    const float* basis      = (const float*)d_in[1];
    const float* coeff      = (const float*)d_in[2];
    const float* self_w     = (const float*)d_in[3];
    const float* bias       = (const float*)d_in[4];
    const float* W_gates    = (const float*)d_in[5];
    const float* U_gates    = (const float*)d_in[6];
    const float* b_gates    = (const float*)d_in[7];
    const float* rel_emb    = (const float*)d_in[8];
    const float* fc1        = (const float*)d_in[9];
    const float* fc1_b      = (const float*)d_in[10];
    const float* fc2        = (const float*)d_in[11];
    const float* fc2_b      = (const float*)d_in[12];
    const int*   senders    = (const int*)d_in[13];
    const int*   receivers  = (const int*)d_in[14];
    const int*   rel_types  = (const int*)d_in[15];
    const int*   triples    = (const int*)d_in[16];
    float* out = (float*)d_out;

    cudaFuncSetAttribute(k_edge,  cudaFuncAttributeMaxDynamicSharedMemorySize, P_SMEM);
    cudaFuncSetAttribute(k_dense, cudaFuncAttributeMaxDynamicSharedMemorySize, P_SMEM);

    float *p_relw, *p_h, *p_agg, *p_deg, *p_dinv, *p_xW, *p_hU;
    int *p_perm, *p_cnt;
    __half *p_hs, *p_xs1, *p_xs2, *p_ws, *p_sws, *p_gws, *p_gus;
    cudaGetSymbolAddress((void**)&p_relw, g_relw);
    cudaGetSymbolAddress((void**)&p_h,    g_h);
    cudaGetSymbolAddress((void**)&p_agg,  g_agg);
    cudaGetSymbolAddress((void**)&p_deg,  g_deg);
    cudaGetSymbolAddress((void**)&p_dinv, g_deginv);
    cudaGetSymbolAddress((void**)&p_perm, g_perm);
    cudaGetSymbolAddress((void**)&p_cnt,  g_cnt);
    cudaGetSymbolAddress((void**)&p_xW,   g_xW);
    cudaGetSymbolAddress((void**)&p_hU,   g_hU);
    cudaGetSymbolAddress((void**)&p_hs,   g_hs);
    cudaGetSymbolAddress((void**)&p_xs1,  g_xs1);
    cudaGetSymbolAddress((void**)&p_xs2,  g_xs2);
    cudaGetSymbolAddress((void**)&p_ws,   g_ws);
    cudaGetSymbolAddress((void**)&p_sws,  g_sws);
    cudaGetSymbolAddress((void**)&p_gws,  g_gws);
    cudaGetSymbolAddress((void**)&p_gus,  g_gus);

    k_relw<<<(NL*DIM*DIM + 255)/256, 256>>>(basis, coeff);
    k_splitw<<<dim3(256, 1, NL*RR), 256>>>(p_relw, p_ws, DIM, DIM,
                                           (size_t)DIM*DIM, (size_t)256*XROW);
    k_splitw<<<dim3(256, 1, NL), 256>>>(self_w, p_sws, DIM, DIM,
                                        (size_t)DIM*DIM, (size_t)256*XROW);
    k_splitw<<<dim3(GNPAD, 1, 1), 256>>>(W_gates, p_gws, D3, D3, 0, 0);
    k_splitw<<<dim3(GNPAD, 1, 1), 256>>>(U_gates, p_gus, D3, D3, 0, 0);
    k_splitx<<<(N_ENT*256 + 255)/256, 256>>>(entity_emb, p_hs);
    k_copy<<<1024, 256>>>(p_h, entity_emb, N_ENT*DIM);

    for (int t = 0; t < NT; ++t) {
        const int* snd = senders   + (size_t)t*NE;
        const int* rcv = receivers + (size_t)t*NE;
        const int* rlt = rel_types + (size_t)t*NE;

        k_zerof<<<256, 256>>>(p_deg, N_ENT);
        k_deg_acc<<<512, 256>>>(rcv);
        k_deginv<<<(N_ENT + 255)/256, 256>>>();

        k_filli<<<512, 256>>>(p_perm, EPADTOT, -1);
        k_filli<<<1, 32>>>(p_cnt, RR, 0);
        k_hist<<<256, 256>>>(rlt);
        k_scan<<<1, 1>>>();
        k_scatter<<<512, 256>>>(rlt);

        const __half* xin = p_hs;
        __half* xout[2] = { p_xs1, p_xs2 };
        for (int l = 0; l < NL; ++l) {
            k_zerof<<<1024, 256>>>(p_agg, N_ENT*DIM);
            k_edge<<<dim3(EGRID, 2), 512, P_SMEM>>>(xin, p_ws + (size_t)l*RR*256*XROW,
                                                    snd, rcv, rlt);
            k_dense<<<dim3(MTILES, 2), 512, P_SMEM>>>(
                xin, p_sws + (size_t)l*256*XROW, N_ENT, 1, DIM,
                nullptr, 0, p_agg, p_dinv, bias + (size_t)l*DIM, xout[l]);
            xin = xout[l];
        }
        k_dense<<<dim3(MTILES, 5), 512, P_SMEM>>>(
            p_xs2, p_gws, N_ENT, 0, D3, p_xW, D3, nullptr, nullptr, nullptr, nullptr);
        k_dense<<<dim3(MTILES, 5), 512, P_SMEM>>>(
            p_hs, p_gus, N_ENT, 0, D3, p_hU, D3, nullptr, nullptr, nullptr, nullptr);
        k_gru<<<(N_ENT*DIM + 255)/256, 256>>>(b_gates);
    }

    k_score<<<NQ/32, 256>>>(triples, rel_emb, fc1, fc1_b, fc2, fc2_b, out);
}

// round 9
// speedup vs baseline: 2.2895x; 1.0914x over previous
#include <cuda_runtime.h>
#include <cuda_fp16.h>
#include <math.h>
#include <stdint.h>

#define N_ENT 20000
#define DIM   200
#define RR    20
#define NB    20
#define NL    2
#define NT    2
#define NE    250000
#define NQ    8192
#define HID   256
#define D3    600

#define BM 128
#define EGRID 1973
#define EPADTOT (EGRID*BM)
#define MTILES 157
#define GNPAD 640
#define XROW 512              // halves per row: 256 hi + 256 lo
#define NSLAB 7               // 7*32 = 224 >= 200

#define XS 64.0f
#define WS 2048.0f
#define SCALE_INV (1.0f/131072.0f)

// dynamic smem (bytes): A[2 stages][2 parts][128 rows][80], B[2 stages][1 part][128][80]
#define A_STG 20480
#define PART_STRIDE 10240
#define OFF_B 40960
#define B_STG 10240
#define OFF_SRC 61440
#define OFF_RCV 61952
#define P_SMEM 62464

// ---------------- device scratch ----------------
__device__ __align__(16) float g_relw[NL*RR*DIM*DIM];
__device__ __align__(16) float g_h  [N_ENT*DIM];
__device__ __align__(16) float g_agg[N_ENT*DIM];
__device__ __align__(16) float g_xW [N_ENT*D3];
__device__ __align__(16) float g_hU [N_ENT*D3];
__device__ float g_deg[N_ENT];
__device__ float g_deginv[N_ENT];
__device__ int   g_perm[EPADTOT];
__device__ int   g_cnt[RR];
__device__ int   g_cur[RR];
__device__ __align__(16) __half g_hs [(size_t)N_ENT*XROW];
__device__ __align__(16) __half g_xs1[(size_t)N_ENT*XROW];
__device__ __align__(16) __half g_xs2[(size_t)N_ENT*XROW];
__device__ __align__(16) __half g_ws [(size_t)NL*RR*256*XROW];
__device__ __align__(16) __half g_sws[(size_t)NL*256*XROW];
__device__ __align__(16) __half g_gws[(size_t)GNPAD*XROW];
__device__ __align__(16) __half g_gus[(size_t)GNPAD*XROW];

// ---------------- helpers ----------------
__device__ __forceinline__ uint32_t smem_u32(const void* p) {
    uint32_t a;
    asm("{ .reg .u64 t; cvta.to.shared.u64 t, %1; cvt.u32.u64 %0, t; }" : "=r"(a) : "l"(p));
    return a;
}
__device__ __forceinline__ void mma16(float* c, const uint32_t* a, uint32_t b0, uint32_t b1) {
    asm volatile(
        "mma.sync.aligned.m16n8k16.row.col.f32.f16.f16.f32 "
        "{%0,%1,%2,%3}, {%4,%5,%6,%7}, {%8,%9}, {%0,%1,%2,%3};"
        : "+f"(c[0]), "+f"(c[1]), "+f"(c[2]), "+f"(c[3])
        : "r"(a[0]), "r"(a[1]), "r"(a[2]), "r"(a[3]), "r"(b0), "r"(b1));
}
__device__ __forceinline__ void ldx4(uint32_t* r, uint32_t addr) {
    asm volatile("ldmatrix.sync.aligned.m8n8.x4.shared.b16 {%0,%1,%2,%3}, [%4];"
        : "=r"(r[0]), "=r"(r[1]), "=r"(r[2]), "=r"(r[3]) : "r"(addr));
}
__device__ __forceinline__ void cpa16(uint32_t dst, const void* src) {
    asm volatile("cp.async.cg.shared.global [%0], [%1], 16;" :: "r"(dst), "l"(src) : "memory");
}
__device__ __forceinline__ void cpa_commit() {
    asm volatile("cp.async.commit_group;" ::: "memory");
}
__device__ __forceinline__ void cpa_wait1() {
    asm volatile("cp.async.wait_group 1;" ::: "memory");
}
__device__ __forceinline__ void cpa_wait0() {
    asm volatile("cp.async.wait_group 0;" ::: "memory");
}
__device__ __forceinline__ void red4(float* p, float a, float b, float c, float d) {
    asm volatile("red.global.add.v4.f32 [%0], {%1,%2,%3,%4};"
                 :: "l"(p), "f"(a), "f"(b), "f"(c), "f"(d) : "memory");
}
__device__ __forceinline__ float sigf(float x) { return 1.f / (1.f + expf(-x)); }

// one k32 slab of 2-pass fp16 mma on stage st (C = A*Bhi exactly: AhBh + AlBh)
// nlim: local column-validity limit within the 128-wide tile (skip dead n-blocks)
__device__ __forceinline__ void slab_mma(uint32_t sb, int st, int wm, int wn, int lane,
                                         int nlim, float (*acc)[4][4]) {
    if (wn >= nlim) return;   // warp-uniform: whole warp-tile dead
    uint32_t abase = sb + st*A_STG;
    uint32_t bbase = sb + OFF_B + st*B_STG;
    int rowoff = (lane & 15)*80 + ((lane >> 4)*16);
#pragma unroll
    for (int kk = 0; kk < 2; ++kk) {
        uint32_t aH[2][4], aL[2][4], bH[2][4];
#pragma unroll
        for (int mi = 0; mi < 2; ++mi) {
            uint32_t ra = abase + (wm + mi*16)*80 + rowoff + kk*32;
            ldx4(aH[mi], ra);
            ldx4(aL[mi], ra + PART_STRIDE);
        }
#pragma unroll
        for (int nj2 = 0; nj2 < 2; ++nj2) {
            if (wn + nj2*16 < nlim) {
                uint32_t rb = bbase + (wn + nj2*16)*80 + rowoff + kk*32;
                ldx4(bH[nj2], rb);
            }
        }
        // x4 on 16(n)x16(k): reg0=(n0-7,k0-7) reg1=(n8-15,k0-7) reg2=(n0-7,k8-15) reg3=(n8-15,k8-15)
#pragma unroll
        for (int mi = 0; mi < 2; ++mi)
#pragma unroll
            for (int nj = 0; nj < 4; ++nj) {
                if (wn + nj*8 >= nlim) continue;
                uint32_t b0 = bH[nj>>1][nj&1], b1 = bH[nj>>1][(nj&1)+2];
                mma16(acc[mi][nj], aH[mi], b0, b1);
                mma16(acc[mi][nj], aL[mi], b0, b1);
            }
    }
}

// ---------------- small utility kernels ----------------
__global__ void k_zerof(float* p, int n) {
    int i = blockIdx.x*blockDim.x + threadIdx.x;
    for (; i < n; i += gridDim.x*blockDim.x) p[i] = 0.f;
}
__global__ void k_filli(int* p, int n, int v) {
    int i = blockIdx.x*blockDim.x + threadIdx.x;
    for (; i < n; i += gridDim.x*blockDim.x) p[i] = v;
}
__global__ void k_copy(float* dst, const float* src, int n) {
    int i = blockIdx.x*blockDim.x + threadIdx.x;
    for (; i < n; i += gridDim.x*blockDim.x) dst[i] = src[i];
}

__global__ void k_relw(const float* __restrict__ basis, const float* __restrict__ coeff) {
    __shared__ float s_co[NL*RR*NB];
    int tid = threadIdx.x;
    for (int i = tid; i < NL*RR*NB; i += blockDim.x) s_co[i] = coeff[i];
    __syncthreads();
    int gid = blockIdx.x*blockDim.x + tid;
    if (gid >= NL*DIM*DIM) return;
    int l = gid / (DIM*DIM);
    int rem = gid % (DIM*DIM);
    int i = rem / DIM, o = rem % DIM;
    float acc[RR];
#pragma unroll
    for (int r = 0; r < RR; ++r) acc[r] = 0.f;
    for (int b = 0; b < NB; ++b) {
        float bv = basis[((l*NB + b)*DIM + i)*DIM + o];
#pragma unroll
        for (int r = 0; r < RR; ++r) acc[r] += s_co[(l*RR + r)*NB + b] * bv;
    }
    for (int r = 0; r < RR; ++r)
        g_relw[((l*RR + r)*DIM + i)*DIM + o] = acc[r];
}

__global__ void k_splitw(const float* __restrict__ src, __half* __restrict__ dst,
                         int Nsrc, int Nvalid, size_t sstride, size_t dstride) {
    int b = blockIdx.z;
    int idx = blockIdx.x*blockDim.x + threadIdx.x;
    int n = idx >> 8, k = idx & 255;
    float v = 0.f;
    if (n < Nvalid && k < DIM) v = src[b*sstride + (size_t)k*Nsrc + n] * WS;
    __half hi = __float2half_rn(v);
    float lo = v - __half2float(hi);
    dst[b*dstride + (size_t)n*XROW + k]       = hi;
    dst[b*dstride + (size_t)n*XROW + 256 + k] = __float2half_rn(lo);
}

__global__ void k_splitx(const float* __restrict__ src, __half* __restrict__ dst) {
    int idx = blockIdx.x*blockDim.x + threadIdx.x;
    if (idx >= N_ENT*256) return;
    int n = idx >> 8, c = idx & 255;
    float v = (c < DIM) ? src[(size_t)n*DIM + c] * XS : 0.f;
    __half hi = __float2half_rn(v);
    float lo = v - __half2float(hi);
    dst[(size_t)n*XROW + c]       = hi;
    dst[(size_t)n*XROW + 256 + c] = __float2half_rn(lo);
}

__global__ void k_deg_acc(const int* __restrict__ rcv) {
    int i = blockIdx.x*blockDim.x + threadIdx.x;
    for (; i < NE; i += gridDim.x*blockDim.x) atomicAdd(&g_deg[rcv[i]], 1.f);
}
__global__ void k_deginv() {
    int i = blockIdx.x*blockDim.x + threadIdx.x;
    if (i < N_ENT) g_deginv[i] = 1.f / fmaxf(g_deg[i], 1.f);
}
__global__ void k_hist(const int* __restrict__ rel) {
    __shared__ int s_cnt[RR];
    int tid = threadIdx.x;
    if (tid < RR) s_cnt[tid] = 0;
    __syncthreads();
    int i = blockIdx.x*blockDim.x + tid;
    for (; i < NE; i += gridDim.x*blockDim.x) atomicAdd(&s_cnt[rel[i]], 1);
    __syncthreads();
    if (tid < RR) atomicAdd(&g_cnt[tid], s_cnt[tid]);
}
__global__ void k_scan() {
    int run = 0;
    for (int r = 0; r < RR; ++r) {
        g_cur[r] = run;
        run += ((g_cnt[r] + BM - 1) / BM) * BM;
    }
}
__global__ void k_scatter(const int* __restrict__ rel) {
    int i = blockIdx.x*blockDim.x + threadIdx.x;
    for (; i < NE; i += gridDim.x*blockDim.x) {
        int r = rel[i];
        int p = atomicAdd(&g_cur[r], 1);
        g_perm[p] = i;
    }
}

// ---------------- edge gather-GEMM-scatter ----------------
__global__ void __launch_bounds__(512, 2)
k_edge(const __half* __restrict__ xs, const __half* __restrict__ wsl,
       const int* __restrict__ snd, const int* __restrict__ rcv,
       const int* __restrict__ relt) {
    extern __shared__ __align__(16) char sm[];
    uint32_t sb = smem_u32(sm);
    int* s_src = (int*)(sm + OFF_SRC);
    int* s_rcv = (int*)(sm + OFF_RCV);
    int tid = threadIdx.x, lane = tid & 31, w = tid >> 5;

    int e0 = g_perm[blockIdx.x*BM];
    if (e0 < 0) return;
    int rel = relt[e0];
    if (tid < BM) {
        int e = g_perm[blockIdx.x*BM + tid];
        int sv = 0, rv = -1;
        if (e >= 0) { sv = snd[e]; rv = rcv[e]; }
        s_src[tid] = sv; s_rcv[tid] = rv;
    }
    __syncthreads();

    const __half* wr = wsl + (size_t)rel * (256*XROW);
    int n0 = blockIdx.y * BM;
    int nlim = DIM - n0; if (nlim > BM) nlim = BM;
    int wm = (w & 3)*32, wn = (w >> 2)*32;
    int grp = lane >> 2, qid = lane & 3;

    float acc[2][4][4];
#pragma unroll
    for (int a = 0; a < 2; ++a)
#pragma unroll
        for (int b = 0; b < 4; ++b)
#pragma unroll
            for (int c = 0; c < 4; ++c) acc[a][b][c] = 0.f;

#define E_ISSUE(s, st)                                                           \
    {                                                                            \
        for (int j = tid; j < 1536; j += 512) {                                  \
            if (j < 1024) {                                                      \
                int part = j >> 9, q = j & 511, row = q >> 2, ch = q & 3;        \
                cpa16(sb + (st)*A_STG + part*PART_STRIDE + row*80 + ch*16,       \
                      xs + (size_t)s_src[row]*XROW + part*256 + (s)*32 + ch*8);  \
            } else {                                                             \
                int q = j - 1024, row = q >> 2, ch = q & 3;                      \
                cpa16(sb + OFF_B + (st)*B_STG + row*80 + ch*16,                  \
                      wr + (size_t)(n0 + row)*XROW + (s)*32 + ch*8);             \
            }                                                                    \
        }                                                                        \
        cpa_commit();                                                            \
    }

    E_ISSUE(0, 0);
    for (int s = 0; s < NSLAB; ++s) {
        if (s + 1 < NSLAB) { E_ISSUE(s + 1, (s + 1) & 1); cpa_wait1(); }
        else cpa_wait0();
        __syncthreads();
        slab_mma(sb, s & 1, wm, wn, lane, nlim, acc);
        __syncthreads();
    }
#undef E_ISSUE

    // scatter epilogue: butterfly-shuffle to 4-consecutive cols, then red.v4
#pragma unroll
    for (int mi = 0; mi < 2; ++mi) {
        int r_e = wm + mi*16 + grp;
        int rv_e = s_rcv[r_e], rv_o = s_rcv[r_e + 8];
#pragma unroll
        for (int nj = 0; nj < 4; ++nj) {
            if (wn + nj*8 >= nlim) continue;
            float* c = acc[mi][nj];
            float e0 = __shfl_xor_sync(0xffffffffu, c[0], 1);
            float e1 = __shfl_xor_sync(0xffffffffu, c[1], 1);
            float e2 = __shfl_xor_sync(0xffffffffu, c[2], 1);
            float e3 = __shfl_xor_sync(0xffffffffu, c[3], 1);
            int colb = n0 + wn + nj*8 + (qid & ~1)*2;
            if ((qid & 1) == 0) {
                if (rv_e >= 0)
                    red4(g_agg + (size_t)rv_e*DIM + colb,
                         c[0]*SCALE_INV, c[1]*SCALE_INV, e0*SCALE_INV, e1*SCALE_INV);
            } else {
                if (rv_o >= 0)
                    red4(g_agg + (size_t)rv_o*DIM + colb,
                         e2*SCALE_INV, e3*SCALE_INV, c[2]*SCALE_INV, c[3]*SCALE_INV);
            }
        }
    }
}

// ---------------- dense GEMM ----------------
__global__ void __launch_bounds__(512, 2)
k_dense(const __half* __restrict__ Axs, const __half* __restrict__ Bws,
        int M, int mode, int Nvalid,
        float* __restrict__ C, int ldC,
        const float* __restrict__ agg, const float* __restrict__ dinv,
        const float* __restrict__ bias, __half* __restrict__ out_xs) {
    extern __shared__ __align__(16) char sm[];
    uint32_t sb = smem_u32(sm);
    int tid = threadIdx.x, lane = tid & 31, w = tid >> 5;
    int m0 = blockIdx.x * BM;
    int n0 = blockIdx.y * BM;
    int nlim = Nvalid - n0; if (nlim > BM) nlim = BM; if (nlim < 0) nlim = 0;
    int wm = (w & 3)*32, wn = (w >> 2)*32;
    int grp = lane >> 2, qid = lane & 3;

    float acc[2][4][4];
#pragma unroll
    for (int a = 0; a < 2; ++a)
#pragma unroll
        for (int b = 0; b < 4; ++b)
#pragma unroll
            for (int c = 0; c < 4; ++c) acc[a][b][c] = 0.f;

#define D_ISSUE(s, st)                                                           \
    {                                                                            \
        for (int j = tid; j < 1536; j += 512) {                                  \
            if (j < 1024) {                                                      \
                int part = j >> 9, q = j & 511, row = q >> 2, ch = q & 3;        \
                int gm = m0 + row; if (gm >= M) gm = 0;                          \
                cpa16(sb + (st)*A_STG + part*PART_STRIDE + row*80 + ch*16,       \
                      Axs + (size_t)gm*XROW + part*256 + (s)*32 + ch*8);         \
            } else {                                                             \
                int q = j - 1024, row = q >> 2, ch = q & 3;                      \
                cpa16(sb + OFF_B + (st)*B_STG + row*80 + ch*16,                  \
                      Bws + (size_t)(n0 + row)*XROW + (s)*32 + ch*8);            \
            }                                                                    \
        }                                                                        \
        cpa_commit();                                                            \
    }

    D_ISSUE(0, 0);
    for (int s = 0; s < NSLAB; ++s) {
        if (s + 1 < NSLAB) { D_ISSUE(s + 1, (s + 1) & 1); cpa_wait1(); }
        else cpa_wait0();
        __syncthreads();
        slab_mma(sb, s & 1, wm, wn, lane, nlim, acc);
        __syncthreads();
    }
#undef D_ISSUE

#pragma unroll
    for (int mi = 0; mi < 2; ++mi) {
        int r0 = m0 + wm + mi*16 + grp;
        int r1 = r0 + 8;
#pragma unroll
        for (int nj = 0; nj < 4; ++nj) {
            if (wn + nj*8 >= nlim) continue;   // dead n-block: pad stays zero-init
            int col = n0 + wn + nj*8 + qid*2;
            float* c = acc[mi][nj];
            if (mode == 0) {
                if (col >= Nvalid) continue;
                if (r0 < M) *(float2*)(C + (size_t)r0*ldC + col) =
                    make_float2(c[0]*SCALE_INV, c[1]*SCALE_INV);
                if (r1 < M) *(float2*)(C + (size_t)r1*ldC + col) =
                    make_float2(c[2]*SCALE_INV, c[3]*SCALE_INV);
            } else {
#pragma unroll
                for (int h = 0; h < 2; ++h) {
                    int row = h ? r1 : r0;
                    if (row >= M) continue;
                    float v0 = 0.f, v1 = 0.f;
                    if (col < DIM) {
                        float dv = dinv[row];
                        float a0 = agg[(size_t)row*DIM + col]*dv + bias[col];
                        float a1 = agg[(size_t)row*DIM + col + 1]*dv + bias[col + 1];
                        v0 = fmaxf(c[h*2+0]*SCALE_INV + a0, 0.f) * XS;
                        v1 = fmaxf(c[h*2+1]*SCALE_INV + a1, 0.f) * XS;
                    }
                    __half h0 = __float2half_rn(v0), h1 = __float2half_rn(v1);
                    float l0 = v0 - __half2float(h0), l1 = v1 - __half2float(h1);
                    *(__half2*)(out_xs + (size_t)row*XROW + col) = __halves2half2(h0, h1);
                    *(__half2*)(out_xs + (size_t)row*XROW + 256 + col) =
                        __halves2half2(__float2half_rn(l0), __float2half_rn(l1));
                }
            }
        }
    }
}

__global__ void k_gru(const float* __restrict__ bg) {
    int idx = blockIdx.x*blockDim.x + threadIdx.x;
    if (idx >= N_ENT*DIM) return;
    int n = idx / DIM, c = idx % DIM;
    size_t b = (size_t)n*D3;
    float r  = sigf(g_xW[b + c]        + g_hU[b + c]        + bg[c]);
    float z  = sigf(g_xW[b + DIM + c]  + g_hU[b + DIM + c]  + bg[DIM + c]);
    float hu3 = g_hU[b + 2*DIM + c];
    float ht = tanhf(g_xW[b + 2*DIM + c] + hu3 + bg[2*DIM + c] + r * hu3);
    float h0 = g_h[idx];
    float hn = (1.f - z)*h0 + z*ht;
    g_h[idx] = hn;
    float X = hn * XS;
    __half hi = __float2half_rn(X);
    float lo = X - __half2float(hi);
    g_hs[(size_t)n*XROW + c]       = hi;
    g_hs[(size_t)n*XROW + 256 + c] = __float2half_rn(lo);
}

__global__ void __launch_bounds__(256)
k_score(const int* __restrict__ triples, const float* __restrict__ rel_emb,
        const float* __restrict__ fc1, const float* __restrict__ b1,
        const float* __restrict__ fc2, const float* __restrict__ fc2b,
        float* __restrict__ out) {
    __shared__ float As[32][8];
    __shared__ float Bs[8][HID];
    __shared__ int s_s[32], s_r[32], s_o[32];
    int tid = threadIdx.x;
    int qbase = blockIdx.x * 32;
    if (tid < 32) {
        s_s[tid] = triples[(qbase + tid)*3 + 0];
        s_r[tid] = triples[(qbase + tid)*3 + 1];
        s_o[tid] = triples[(qbase + tid)*3 + 2];
    }
    __syncthreads();
    int w = tid >> 5, lane = tid & 31;
    float acc[4][8];
#pragma unroll
    for (int i = 0; i < 4; ++i)
#pragma unroll
        for (int j = 0; j < 8; ++j) acc[i][j] = 0.f;

    for (int k0 = 0; k0 < D3; k0 += 8) {
        {
            int qi = tid >> 3, kk = tid & 7, k = k0 + kk;
            float v;
            if (k < DIM)            v = g_h[(size_t)s_s[qi]*DIM + k];
            else if (k < 2*DIM)     v = rel_emb[(size_t)s_r[qi]*DIM + (k - DIM)];
            else                    v = g_h[(size_t)s_o[qi]*DIM + (k - 2*DIM)];
            As[qi][kk] = v;
        }
        {
            int kr = tid >> 5, cb = tid & 31;
#pragma unroll
            for (int j = 0; j < 8; ++j)
                Bs[kr][cb + 32*j] = fc1[(size_t)(k0 + kr)*HID + cb + 32*j];
        }
        __syncthreads();
#pragma unroll
        for (int kk = 0; kk < 8; ++kk) {
#pragma unroll
            for (int i = 0; i < 4; ++i) {
                float a = As[w*4 + i][kk];
#pragma unroll
                for (int j = 0; j < 8; ++j)
                    acc[i][j] += a * Bs[kk][lane + 32*j];
            }
        }
        __syncthreads();
    }
#pragma unroll
    for (int i = 0; i < 4; ++i) {
        float p = 0.f;
#pragma unroll
        for (int j = 0; j < 8; ++j) {
            int col = lane + 32*j;
            float hv = fmaxf(acc[i][j] + b1[col], 0.f);
            p += hv * fc2[col];
        }
#pragma unroll
        for (int off = 16; off > 0; off >>= 1)
            p += __shfl_down_sync(0xffffffffu, p, off);
        if (lane == 0) out[qbase + w*4 + i] = p + fc2b[0];
    }
}

// ---------------- host ----------------
extern "C" void kernel_launch(void* const* d_in, const int* in_sizes, int n_in,
                              void* d_out, int out_size) {
    const float* entity_emb = (const float*)d_in[0];
    const float* basis      = (const float*)d_in[1];
    const float* coeff      = (const float*)d_in[2];
    const float* self_w     = (const float*)d_in[3];
    const float* bias       = (const float*)d_in[4];
    const float* W_gates    = (const float*)d_in[5];
    const float* U_gates    = (const float*)d_in[6];
    const float* b_gates    = (const float*)d_in[7];
    const float* rel_emb    = (const float*)d_in[8];
    const float* fc1        = (const float*)d_in[9];
    const float* fc1_b      = (const float*)d_in[10];
    const float* fc2        = (const float*)d_in[11];
    const float* fc2_b      = (const float*)d_in[12];
    const int*   senders    = (const int*)d_in[13];
    const int*   receivers  = (const int*)d_in[14];
    const int*   rel_types  = (const int*)d_in[15];
    const int*   triples    = (const int*)d_in[16];
    float* out = (float*)d_out;

    cudaFuncSetAttribute(k_edge,  cudaFuncAttributeMaxDynamicSharedMemorySize, P_SMEM);
    cudaFuncSetAttribute(k_dense, cudaFuncAttributeMaxDynamicSharedMemorySize, P_SMEM);

    float *p_relw, *p_h, *p_agg, *p_deg, *p_dinv, *p_xW, *p_hU;
    int *p_perm, *p_cnt;
    __half *p_hs, *p_xs1, *p_xs2, *p_ws, *p_sws, *p_gws, *p_gus;
    cudaGetSymbolAddress((void**)&p_relw, g_relw);
    cudaGetSymbolAddress((void**)&p_h,    g_h);
    cudaGetSymbolAddress((void**)&p_agg,  g_agg);
    cudaGetSymbolAddress((void**)&p_deg,  g_deg);
    cudaGetSymbolAddress((void**)&p_dinv, g_deginv);
    cudaGetSymbolAddress((void**)&p_perm, g_perm);
    cudaGetSymbolAddress((void**)&p_cnt,  g_cnt);
    cudaGetSymbolAddress((void**)&p_xW,   g_xW);
    cudaGetSymbolAddress((void**)&p_hU,   g_hU);
    cudaGetSymbolAddress((void**)&p_hs,   g_hs);
    cudaGetSymbolAddress((void**)&p_xs1,  g_xs1);
    cudaGetSymbolAddress((void**)&p_xs2,  g_xs2);
    cudaGetSymbolAddress((void**)&p_ws,   g_ws);
    cudaGetSymbolAddress((void**)&p_sws,  g_sws);
    cudaGetSymbolAddress((void**)&p_gws,  g_gws);
    cudaGetSymbolAddress((void**)&p_gus,  g_gus);

    k_relw<<<(NL*DIM*DIM + 255)/256, 256>>>(basis, coeff);
    k_splitw<<<dim3(256, 1, NL*RR), 256>>>(p_relw, p_ws, DIM, DIM,
                                           (size_t)DIM*DIM, (size_t)256*XROW);
    k_splitw<<<dim3(256, 1, NL), 256>>>(self_w, p_sws, DIM, DIM,
                                        (size_t)DIM*DIM, (size_t)256*XROW);
    k_splitw<<<dim3(GNPAD, 1, 1), 256>>>(W_gates, p_gws, D3, D3, 0, 0);
    k_splitw<<<dim3(GNPAD, 1, 1), 256>>>(U_gates, p_gus, D3, D3, 0, 0);
    k_splitx<<<(N_ENT*256 + 255)/256, 256>>>(entity_emb, p_hs);
    k_copy<<<1024, 256>>>(p_h, entity_emb, N_ENT*DIM);

    for (int t = 0; t < NT; ++t) {
        const int* snd = senders   + (size_t)t*NE;
        const int* rcv = receivers + (size_t)t*NE;
        const int* rlt = rel_types + (size_t)t*NE;

        k_zerof<<<256, 256>>>(p_deg, N_ENT);
        k_deg_acc<<<512, 256>>>(rcv);
        k_deginv<<<(N_ENT + 255)/256, 256>>>();

        k_filli<<<512, 256>>>(p_perm, EPADTOT, -1);
        k_filli<<<1, 32>>>(p_cnt, RR, 0);
        k_hist<<<256, 256>>>(rlt);
        k_scan<<<1, 1>>>();
        k_scatter<<<512, 256>>>(rlt);

        const __half* xin = p_hs;
        __half* xout[2] = { p_xs1, p_xs2 };
        for (int l = 0; l < NL; ++l) {
            k_zerof<<<1024, 256>>>(p_agg, N_ENT*DIM);
            k_edge<<<dim3(EGRID, 2), 512, P_SMEM>>>(xin, p_ws + (size_t)l*RR*256*XROW,
                                                    snd, rcv, rlt);
            k_dense<<<dim3(MTILES, 2), 512, P_SMEM>>>(
                xin, p_sws + (size_t)l*256*XROW, N_ENT, 1, DIM,
                nullptr, 0, p_agg, p_dinv, bias + (size_t)l*DIM, xout[l]);
            xin = xout[l];
        }
        k_dense<<<dim3(MTILES, 5), 512, P_SMEM>>>(
            p_xs2, p_gws, N_ENT, 0, D3, p_xW, D3, nullptr, nullptr, nullptr, nullptr);
        k_dense<<<dim3(MTILES, 5), 512, P_SMEM>>>(
            p_hs, p_gus, N_ENT, 0, D3, p_hU, D3, nullptr, nullptr, nullptr, nullptr);
        k_gru<<<(N_ENT*DIM + 255)/256, 256>>>(b_gates);
    }

    k_score<<<NQ/32, 256>>>(triples, rel_emb, fc1, fc1_b, fc2, fc2_b, out);
}

// round 10
// speedup vs baseline: 2.7007x; 1.1796x over previous
#include <cuda_runtime.h>
#include <cuda_fp16.h>
#include <math.h>
#include <stdint.h>

#define N_ENT 20000
#define DIM   200
#define RR    20
#define NB    20
#define NL    2
#define NT    2
#define NE    250000
#define NQ    8192
#define HID   256
#define D3    600

#define BM 128
#define EGRID 1973
#define EPADTOT (EGRID*BM)
#define MTILES 157
#define GNPAD 640
#define XROW 512              // halves per row: 256 hi + 256 lo
#define NSLAB 7               // 7*32 = 224 >= 200

#define XS 64.0f
#define WS 2048.0f
#define SCALE_INV (1.0f/131072.0f)

// dynamic smem (bytes): A[3 stages][2 parts][128 rows][80], B[3 stages][128][80], idx
#define A_STG 20480
#define PART_STRIDE 10240
#define OFF_B 61440
#define B_STG 10240
#define OFF_SRC 92160
#define OFF_RCV 92672
#define P_SMEM 93184

// ---------------- device scratch ----------------
__device__ __align__(16) float g_relw[NL*RR*DIM*DIM];
__device__ __align__(16) float g_h  [N_ENT*DIM];
__device__ __align__(16) float g_agg[N_ENT*DIM];
__device__ __align__(16) float g_xW [N_ENT*D3];
__device__ __align__(16) float g_hU [N_ENT*D3];
__device__ float g_deg[N_ENT];
__device__ float g_deginv[N_ENT];
__device__ int   g_perm[EPADTOT];
__device__ int   g_cnt[RR];
__device__ int   g_cur[RR];
__device__ __align__(16) __half g_hs [(size_t)N_ENT*XROW];
__device__ __align__(16) __half g_xs1[(size_t)N_ENT*XROW];
__device__ __align__(16) __half g_xs2[(size_t)N_ENT*XROW];
__device__ __align__(16) __half g_ws [(size_t)NL*RR*256*XROW];
__device__ __align__(16) __half g_sws[(size_t)NL*256*XROW];
__device__ __align__(16) __half g_gws[(size_t)GNPAD*XROW];
__device__ __align__(16) __half g_gus[(size_t)GNPAD*XROW];

// ---------------- helpers ----------------
__device__ __forceinline__ uint32_t smem_u32(const void* p) {
    uint32_t a;
    asm("{ .reg .u64 t; cvta.to.shared.u64 t, %1; cvt.u32.u64 %0, t; }" : "=r"(a) : "l"(p));
    return a;
}
__device__ __forceinline__ void mma16(float* c, const uint32_t* a, uint32_t b0, uint32_t b1) {
    asm volatile(
        "mma.sync.aligned.m16n8k16.row.col.f32.f16.f16.f32 "
        "{%0,%1,%2,%3}, {%4,%5,%6,%7}, {%8,%9}, {%0,%1,%2,%3};"
        : "+f"(c[0]), "+f"(c[1]), "+f"(c[2]), "+f"(c[3])
        : "r"(a[0]), "r"(a[1]), "r"(a[2]), "r"(a[3]), "r"(b0), "r"(b1));
}
__device__ __forceinline__ void ldx4(uint32_t* r, uint32_t addr) {
    asm volatile("ldmatrix.sync.aligned.m8n8.x4.shared.b16 {%0,%1,%2,%3}, [%4];"
        : "=r"(r[0]), "=r"(r[1]), "=r"(r[2]), "=r"(r[3]) : "r"(addr));
}
__device__ __forceinline__ void cpa16(uint32_t dst, const void* src) {
    asm volatile("cp.async.cg.shared.global [%0], [%1], 16;" :: "r"(dst), "l"(src) : "memory");
}
__device__ __forceinline__ void cpa_commit() {
    asm volatile("cp.async.commit_group;" ::: "memory");
}
__device__ __forceinline__ void cpa_wait1() {
    asm volatile("cp.async.wait_group 1;" ::: "memory");
}
__device__ __forceinline__ void cpa_wait0() {
    asm volatile("cp.async.wait_group 0;" ::: "memory");
}
__device__ __forceinline__ void red4(float* p, float a, float b, float c, float d) {
    asm volatile("red.global.add.v4.f32 [%0], {%1,%2,%3,%4};"
                 :: "l"(p), "f"(a), "f"(b), "f"(c), "f"(d) : "memory");
}
__device__ __forceinline__ float sigf(float x) { return 1.f / (1.f + expf(-x)); }

// one k32 slab of 2-pass fp16 mma on stage st (C = A*Bhi exactly: AhBh + AlBh)
__device__ __forceinline__ void slab_mma(uint32_t sb, int st, int wm, int wn, int lane,
                                         int nlim, float (*acc)[4][4]) {
    if (wn >= nlim) return;   // warp-uniform: whole warp-tile dead
    uint32_t abase = sb + st*A_STG;
    uint32_t bbase = sb + OFF_B + st*B_STG;
    int rowoff = (lane & 15)*80 + ((lane >> 4)*16);
#pragma unroll
    for (int kk = 0; kk < 2; ++kk) {
        uint32_t aH[2][4], aL[2][4], bH[2][4];
#pragma unroll
        for (int mi = 0; mi < 2; ++mi) {
            uint32_t ra = abase + (wm + mi*16)*80 + rowoff + kk*32;
            ldx4(aH[mi], ra);
            ldx4(aL[mi], ra + PART_STRIDE);
        }
#pragma unroll
        for (int nj2 = 0; nj2 < 2; ++nj2) {
            if (wn + nj2*16 < nlim) {
                uint32_t rb = bbase + (wn + nj2*16)*80 + rowoff + kk*32;
                ldx4(bH[nj2], rb);
            }
        }
        // x4 on 16(n)x16(k): reg0=(n0-7,k0-7) reg1=(n8-15,k0-7) reg2=(n0-7,k8-15) reg3=(n8-15,k8-15)
#pragma unroll
        for (int mi = 0; mi < 2; ++mi)
#pragma unroll
            for (int nj = 0; nj < 4; ++nj) {
                if (wn + nj*8 >= nlim) continue;
                uint32_t b0 = bH[nj>>1][nj&1], b1 = bH[nj>>1][(nj&1)+2];
                mma16(acc[mi][nj], aH[mi], b0, b1);
                mma16(acc[mi][nj], aL[mi], b0, b1);
            }
    }
}

// ---------------- small utility kernels ----------------
__global__ void k_zerof(float* p, int n) {
    int i = blockIdx.x*blockDim.x + threadIdx.x;
    for (; i < n; i += gridDim.x*blockDim.x) p[i] = 0.f;
}
__global__ void k_copy(float* dst, const float* src, int n) {
    int i = blockIdx.x*blockDim.x + threadIdx.x;
    for (; i < n; i += gridDim.x*blockDim.x) dst[i] = src[i];
}
// fused per-timestep setup: perm=-1, deg=0, cnt=0
__global__ void k_setup() {
    int i = blockIdx.x*blockDim.x + threadIdx.x;
    int stride = gridDim.x*blockDim.x;
    for (int j = i; j < EPADTOT; j += stride) g_perm[j] = -1;
    for (int j = i; j < N_ENT; j += stride) g_deg[j] = 0.f;
    if (i < RR) g_cnt[i] = 0;
}

__global__ void k_relw(const float* __restrict__ basis, const float* __restrict__ coeff) {
    __shared__ float s_co[NL*RR*NB];
    int tid = threadIdx.x;
    for (int i = tid; i < NL*RR*NB; i += blockDim.x) s_co[i] = coeff[i];
    __syncthreads();
    int gid = blockIdx.x*blockDim.x + tid;
    if (gid >= NL*DIM*DIM) return;
    int l = gid / (DIM*DIM);
    int rem = gid % (DIM*DIM);
    int i = rem / DIM, o = rem % DIM;
    float acc[RR];
#pragma unroll
    for (int r = 0; r < RR; ++r) acc[r] = 0.f;
    for (int b = 0; b < NB; ++b) {
        float bv = basis[((l*NB + b)*DIM + i)*DIM + o];
#pragma unroll
        for (int r = 0; r < RR; ++r) acc[r] += s_co[(l*RR + r)*NB + b] * bv;
    }
    for (int r = 0; r < RR; ++r)
        g_relw[((l*RR + r)*DIM + i)*DIM + o] = acc[r];
}

__global__ void k_splitw(const float* __restrict__ src, __half* __restrict__ dst,
                         int Nsrc, int Nvalid, size_t sstride, size_t dstride) {
    int b = blockIdx.z;
    int idx = blockIdx.x*blockDim.x + threadIdx.x;
    int n = idx >> 8, k = idx & 255;
    float v = 0.f;
    if (n < Nvalid && k < DIM) v = src[b*sstride + (size_t)k*Nsrc + n] * WS;
    __half hi = __float2half_rn(v);
    float lo = v - __half2float(hi);
    dst[b*dstride + (size_t)n*XROW + k]       = hi;
    dst[b*dstride + (size_t)n*XROW + 256 + k] = __float2half_rn(lo);
}

__global__ void k_splitx(const float* __restrict__ src, __half* __restrict__ dst) {
    int idx = blockIdx.x*blockDim.x + threadIdx.x;
    if (idx >= N_ENT*256) return;
    int n = idx >> 8, c = idx & 255;
    float v = (c < DIM) ? src[(size_t)n*DIM + c] * XS : 0.f;
    __half hi = __float2half_rn(v);
    float lo = v - __half2float(hi);
    dst[(size_t)n*XROW + c]       = hi;
    dst[(size_t)n*XROW + 256 + c] = __float2half_rn(lo);
}

__global__ void k_deg_acc(const int* __restrict__ rcv) {
    int i = blockIdx.x*blockDim.x + threadIdx.x;
    for (; i < NE; i += gridDim.x*blockDim.x) atomicAdd(&g_deg[rcv[i]], 1.f);
}
__global__ void k_deginv() {
    int i = blockIdx.x*blockDim.x + threadIdx.x;
    if (i < N_ENT) g_deginv[i] = 1.f / fmaxf(g_deg[i], 1.f);
}
__global__ void k_hist(const int* __restrict__ rel) {
    __shared__ int s_cnt[RR];
    int tid = threadIdx.x;
    if (tid < RR) s_cnt[tid] = 0;
    __syncthreads();
    int i = blockIdx.x*blockDim.x + tid;
    for (; i < NE; i += gridDim.x*blockDim.x) atomicAdd(&s_cnt[rel[i]], 1);
    __syncthreads();
    if (tid < RR) atomicAdd(&g_cnt[tid], s_cnt[tid]);
}
__global__ void k_scan() {
    int run = 0;
    for (int r = 0; r < RR; ++r) {
        g_cur[r] = run;
        run += ((g_cnt[r] + BM - 1) / BM) * BM;
    }
}
__global__ void k_scatter(const int* __restrict__ rel) {
    int i = blockIdx.x*blockDim.x + threadIdx.x;
    for (; i < NE; i += gridDim.x*blockDim.x) {
        int r = rel[i];
        int p = atomicAdd(&g_cur[r], 1);
        g_perm[p] = i;
    }
}

// ---------------- edge gather-GEMM-scatter ----------------
__global__ void __launch_bounds__(512, 2)
k_edge(const __half* __restrict__ xs, const __half* __restrict__ wsl,
       const int* __restrict__ snd, const int* __restrict__ rcv,
       const int* __restrict__ relt) {
    extern __shared__ __align__(16) char sm[];
    uint32_t sb = smem_u32(sm);
    int* s_src = (int*)(sm + OFF_SRC);
    int* s_rcv = (int*)(sm + OFF_RCV);
    int tid = threadIdx.x, lane = tid & 31, w = tid >> 5;

    int e0 = g_perm[blockIdx.x*BM];
    if (e0 < 0) return;
    int rel = relt[e0];
    if (tid < BM) {
        int e = g_perm[blockIdx.x*BM + tid];
        int sv = 0, rv = -1;
        if (e >= 0) { sv = snd[e]; rv = rcv[e]; }
        s_src[tid] = sv; s_rcv[tid] = rv;
    }
    __syncthreads();

    const __half* wr = wsl + (size_t)rel * (256*XROW);
    int n0 = blockIdx.y * BM;
    int nlim = DIM - n0; if (nlim > BM) nlim = BM;
    int wm = (w & 3)*32, wn = (w >> 2)*32;
    int grp = lane >> 2, qid = lane & 3;

    float acc[2][4][4];
#pragma unroll
    for (int a = 0; a < 2; ++a)
#pragma unroll
        for (int b = 0; b < 4; ++b)
#pragma unroll
            for (int c = 0; c < 4; ++c) acc[a][b][c] = 0.f;

#define E_ISSUE(s, st)                                                           \
    {                                                                            \
        for (int j = tid; j < 1536; j += 512) {                                  \
            if (j < 1024) {                                                      \
                int part = j >> 9, q = j & 511, row = q >> 2, ch = q & 3;        \
                cpa16(sb + (st)*A_STG + part*PART_STRIDE + row*80 + ch*16,       \
                      xs + (size_t)s_src[row]*XROW + part*256 + (s)*32 + ch*8);  \
            } else {                                                             \
                int q = j - 1024, row = q >> 2, ch = q & 3;                      \
                cpa16(sb + OFF_B + (st)*B_STG + row*80 + ch*16,                  \
                      wr + (size_t)(n0 + row)*XROW + (s)*32 + ch*8);             \
            }                                                                    \
        }                                                                        \
        cpa_commit();                                                            \
    }

    E_ISSUE(0, 0);
    E_ISSUE(1, 1);
#pragma unroll
    for (int s = 0; s < NSLAB; ++s) {
        if (s + 1 < NSLAB) cpa_wait1(); else cpa_wait0();
        __syncthreads();                        // single barrier per slab
        if (s + 2 < NSLAB) E_ISSUE(s + 2, (s + 2) % 3);
        slab_mma(sb, s % 3, wm, wn, lane, nlim, acc);
    }
#undef E_ISSUE

    // scatter epilogue: butterfly-shuffle to 4-consecutive cols, then red.v4
#pragma unroll
    for (int mi = 0; mi < 2; ++mi) {
        int r_e = wm + mi*16 + grp;
        int rv_e = s_rcv[r_e], rv_o = s_rcv[r_e + 8];
#pragma unroll
        for (int nj = 0; nj < 4; ++nj) {
            if (wn + nj*8 >= nlim) continue;
            float* c = acc[mi][nj];
            float e0f = __shfl_xor_sync(0xffffffffu, c[0], 1);
            float e1f = __shfl_xor_sync(0xffffffffu, c[1], 1);
            float e2f = __shfl_xor_sync(0xffffffffu, c[2], 1);
            float e3f = __shfl_xor_sync(0xffffffffu, c[3], 1);
            int colb = n0 + wn + nj*8 + (qid & ~1)*2;
            if ((qid & 1) == 0) {
                if (rv_e >= 0)
                    red4(g_agg + (size_t)rv_e*DIM + colb,
                         c[0]*SCALE_INV, c[1]*SCALE_INV, e0f*SCALE_INV, e1f*SCALE_INV);
            } else {
                if (rv_o >= 0)
                    red4(g_agg + (size_t)rv_o*DIM + colb,
                         e2f*SCALE_INV, e3f*SCALE_INV, c[2]*SCALE_INV, c[3]*SCALE_INV);
            }
        }
    }
}

// ---------------- dense GEMM ----------------
__global__ void __launch_bounds__(512, 2)
k_dense(const __half* __restrict__ Axs, const __half* __restrict__ Bws,
        int M, int mode, int Nvalid,
        float* __restrict__ C, int ldC,
        const float* __restrict__ agg, const float* __restrict__ dinv,
        const float* __restrict__ bias, __half* __restrict__ out_xs) {
    extern __shared__ __align__(16) char sm[];
    uint32_t sb = smem_u32(sm);
    int tid = threadIdx.x, lane = tid & 31, w = tid >> 5;
    int m0 = blockIdx.x * BM;
    int n0 = blockIdx.y * BM;
    int nlim = Nvalid - n0; if (nlim > BM) nlim = BM; if (nlim < 0) nlim = 0;
    int wm = (w & 3)*32, wn = (w >> 2)*32;
    int grp = lane >> 2, qid = lane & 3;

    float acc[2][4][4];
#pragma unroll
    for (int a = 0; a < 2; ++a)
#pragma unroll
        for (int b = 0; b < 4; ++b)
#pragma unroll
            for (int c = 0; c < 4; ++c) acc[a][b][c] = 0.f;

#define D_ISSUE(s, st)                                                           \
    {                                                                            \
        for (int j = tid; j < 1536; j += 512) {                                  \
            if (j < 1024) {                                                      \
                int part = j >> 9, q = j & 511, row = q >> 2, ch = q & 3;        \
                int gm = m0 + row; if (gm >= M) gm = 0;                          \
                cpa16(sb + (st)*A_STG + part*PART_STRIDE + row*80 + ch*16,       \
                      Axs + (size_t)gm*XROW + part*256 + (s)*32 + ch*8);         \
            } else {                                                             \
                int q = j - 1024, row = q >> 2, ch = q & 3;                      \
                cpa16(sb + OFF_B + (st)*B_STG + row*80 + ch*16,                  \
                      Bws + (size_t)(n0 + row)*XROW + (s)*32 + ch*8);            \
            }                                                                    \
        }                                                                        \
        cpa_commit();                                                            \
    }

    D_ISSUE(0, 0);
    D_ISSUE(1, 1);
#pragma unroll
    for (int s = 0; s < NSLAB; ++s) {
        if (s + 1 < NSLAB) cpa_wait1(); else cpa_wait0();
        __syncthreads();
        if (s + 2 < NSLAB) D_ISSUE(s + 2, (s + 2) % 3);
        slab_mma(sb, s % 3, wm, wn, lane, nlim, acc);
    }
#undef D_ISSUE

#pragma unroll
    for (int mi = 0; mi < 2; ++mi) {
        int r0 = m0 + wm + mi*16 + grp;
        int r1 = r0 + 8;
#pragma unroll
        for (int nj = 0; nj < 4; ++nj) {
            if (wn + nj*8 >= nlim) continue;   // dead n-block: pad stays zero-init
            int col = n0 + wn + nj*8 + qid*2;
            float* c = acc[mi][nj];
            if (mode == 0) {
                if (col >= Nvalid) continue;
                if (r0 < M) *(float2*)(C + (size_t)r0*ldC + col) =
                    make_float2(c[0]*SCALE_INV, c[1]*SCALE_INV);
                if (r1 < M) *(float2*)(C + (size_t)r1*ldC + col) =
                    make_float2(c[2]*SCALE_INV, c[3]*SCALE_INV);
            } else {
#pragma unroll
                for (int h = 0; h < 2; ++h) {
                    int row = h ? r1 : r0;
                    if (row >= M) continue;
                    float v0 = 0.f, v1 = 0.f;
                    if (col < DIM) {
                        float dv = dinv[row];
                        float a0 = agg[(size_t)row*DIM + col]*dv + bias[col];
                        float a1 = agg[(size_t)row*DIM + col + 1]*dv + bias[col + 1];
                        v0 = fmaxf(c[h*2+0]*SCALE_INV + a0, 0.f) * XS;
                        v1 = fmaxf(c[h*2+1]*SCALE_INV + a1, 0.f) * XS;
                    }
                    __half h0 = __float2half_rn(v0), h1 = __float2half_rn(v1);
                    float l0 = v0 - __half2float(h0), l1 = v1 - __half2float(h1);
                    *(__half2*)(out_xs + (size_t)row*XROW + col) = __halves2half2(h0, h1);
                    *(__half2*)(out_xs + (size_t)row*XROW + 256 + col) =
                        __halves2half2(__float2half_rn(l0), __float2half_rn(l1));
                }
            }
        }
    }
}

__global__ void k_gru(const float* __restrict__ bg) {
    int idx = blockIdx.x*blockDim.x + threadIdx.x;
    if (idx >= N_ENT*DIM) return;
    int n = idx / DIM, c = idx % DIM;
    size_t b = (size_t)n*D3;
    float r  = sigf(g_xW[b + c]        + g_hU[b + c]        + bg[c]);
    float z  = sigf(g_xW[b + DIM + c]  + g_hU[b + DIM + c]  + bg[DIM + c]);
    float hu3 = g_hU[b + 2*DIM + c];
    float ht = tanhf(g_xW[b + 2*DIM + c] + hu3 + bg[2*DIM + c] + r * hu3);
    float h0 = g_h[idx];
    float hn = (1.f - z)*h0 + z*ht;
    g_h[idx] = hn;
    float X = hn * XS;
    __half hi = __float2half_rn(X);
    float lo = X - __half2float(hi);
    g_hs[(size_t)n*XROW + c]       = hi;
    g_hs[(size_t)n*XROW + 256 + c] = __float2half_rn(lo);
}

__global__ void __launch_bounds__(256)
k_score(const int* __restrict__ triples, const float* __restrict__ rel_emb,
        const float* __restrict__ fc1, const float* __restrict__ b1,
        const float* __restrict__ fc2, const float* __restrict__ fc2b,
        float* __restrict__ out) {
    __shared__ float As[32][8];
    __shared__ float Bs[8][HID];
    __shared__ int s_s[32], s_r[32], s_o[32];
    int tid = threadIdx.x;
    int qbase = blockIdx.x * 32;
    if (tid < 32) {
        s_s[tid] = triples[(qbase + tid)*3 + 0];
        s_r[tid] = triples[(qbase + tid)*3 + 1];
        s_o[tid] = triples[(qbase + tid)*3 + 2];
    }
    __syncthreads();
    int w = tid >> 5, lane = tid & 31;
    float acc[4][8];
#pragma unroll
    for (int i = 0; i < 4; ++i)
#pragma unroll
        for (int j = 0; j < 8; ++j) acc[i][j] = 0.f;

    for (int k0 = 0; k0 < D3; k0 += 8) {
        {
            int qi = tid >> 3, kk = tid & 7, k = k0 + kk;
            float v;
            if (k < DIM)            v = g_h[(size_t)s_s[qi]*DIM + k];
            else if (k < 2*DIM)     v = rel_emb[(size_t)s_r[qi]*DIM + (k - DIM)];
            else                    v = g_h[(size_t)s_o[qi]*DIM + (k - 2*DIM)];
            As[qi][kk] = v;
        }
        {
            int kr = tid >> 5, cb = tid & 31;
#pragma unroll
            for (int j = 0; j < 8; ++j)
                Bs[kr][cb + 32*j] = fc1[(size_t)(k0 + kr)*HID + cb + 32*j];
        }
        __syncthreads();
#pragma unroll
        for (int kk = 0; kk < 8; ++kk) {
#pragma unroll
            for (int i = 0; i < 4; ++i) {
                float a = As[w*4 + i][kk];
#pragma unroll
                for (int j = 0; j < 8; ++j)
                    acc[i][j] += a * Bs[kk][lane + 32*j];
            }
        }
        __syncthreads();
    }
#pragma unroll
    for (int i = 0; i < 4; ++i) {
        float p = 0.f;
#pragma unroll
        for (int j = 0; j < 8; ++j) {
            int col = lane + 32*j;
            float hv = fmaxf(acc[i][j] + b1[col], 0.f);
            p += hv * fc2[col];
        }
#pragma unroll
        for (int off = 16; off > 0; off >>= 1)
            p += __shfl_down_sync(0xffffffffu, p, off);
        if (lane == 0) out[qbase + w*4 + i] = p + fc2b[0];
    }
}

// ---------------- host ----------------
extern "C" void kernel_launch(void* const* d_in, const int* in_sizes, int n_in,
                              void* d_out, int out_size) {
    const float* entity_emb = (const float*)d_in[0];
    const float* basis      = (const float*)d_in[1];
    const float* coeff      = (const float*)d_in[2];
    const float* self_w     = (const float*)d_in[3];
    const float* bias       = (const float*)d_in[4];
    const float* W_gates    = (const float*)d_in[5];
    const float* U_gates    = (const float*)d_in[6];
    const float* b_gates    = (const float*)d_in[7];
    const float* rel_emb    = (const float*)d_in[8];
    const float* fc1        = (const float*)d_in[9];
    const float* fc1_b      = (const float*)d_in[10];
    const float* fc2        = (const float*)d_in[11];
    const float* fc2_b      = (const float*)d_in[12];
    const int*   senders    = (const int*)d_in[13];
    const int*   receivers  = (const int*)d_in[14];
    const int*   rel_types  = (const int*)d_in[15];
    const int*   triples    = (const int*)d_in[16];
    float* out = (float*)d_out;

    cudaFuncSetAttribute(k_edge,  cudaFuncAttributeMaxDynamicSharedMemorySize, P_SMEM);
    cudaFuncSetAttribute(k_dense, cudaFuncAttributeMaxDynamicSharedMemorySize, P_SMEM);

    float *p_relw, *p_h, *p_agg, *p_dinv, *p_xW, *p_hU;
    __half *p_hs, *p_xs1, *p_xs2, *p_ws, *p_sws, *p_gws, *p_gus;
    cudaGetSymbolAddress((void**)&p_relw, g_relw);
    cudaGetSymbolAddress((void**)&p_h,    g_h);
    cudaGetSymbolAddress((void**)&p_agg,  g_agg);
    cudaGetSymbolAddress((void**)&p_dinv, g_deginv);
    cudaGetSymbolAddress((void**)&p_xW,   g_xW);
    cudaGetSymbolAddress((void**)&p_hU,   g_hU);
    cudaGetSymbolAddress((void**)&p_hs,   g_hs);
    cudaGetSymbolAddress((void**)&p_xs1,  g_xs1);
    cudaGetSymbolAddress((void**)&p_xs2,  g_xs2);
    cudaGetSymbolAddress((void**)&p_ws,   g_ws);
    cudaGetSymbolAddress((void**)&p_sws,  g_sws);
    cudaGetSymbolAddress((void**)&p_gws,  g_gws);
    cudaGetSymbolAddress((void**)&p_gus,  g_gus);

    k_relw<<<(NL*DIM*DIM + 255)/256, 256>>>(basis, coeff);
    k_splitw<<<dim3(256, 1, NL*RR), 256>>>(p_relw, p_ws, DIM, DIM,
                                           (size_t)DIM*DIM, (size_t)256*XROW);
    k_splitw<<<dim3(256, 1, NL), 256>>>(self_w, p_sws, DIM, DIM,
                                        (size_t)DIM*DIM, (size_t)256*XROW);
    k_splitw<<<dim3(GNPAD, 1, 1), 256>>>(W_gates, p_gws, D3, D3, 0, 0);
    k_splitw<<<dim3(GNPAD, 1, 1), 256>>>(U_gates, p_gus, D3, D3, 0, 0);
    k_splitx<<<(N_ENT*256 + 255)/256, 256>>>(entity_emb, p_hs);
    k_copy<<<1024, 256>>>(p_h, entity_emb, N_ENT*DIM);

    for (int t = 0; t < NT; ++t) {
        const int* snd = senders   + (size_t)t*NE;
        const int* rcv = receivers + (size_t)t*NE;
        const int* rlt = rel_types + (size_t)t*NE;

        k_setup<<<512, 256>>>();
        k_deg_acc<<<512, 256>>>(rcv);
        k_deginv<<<(N_ENT + 255)/256, 256>>>();
        k_hist<<<256, 256>>>(rlt);
        k_scan<<<1, 1>>>();
        k_scatter<<<512, 256>>>(rlt);

        const __half* xin = p_hs;
        __half* xout[2] = { p_xs1, p_xs2 };
        for (int l = 0; l < NL; ++l) {
            k_zerof<<<1024, 256>>>(p_agg, N_ENT*DIM);
            k_edge<<<dim3(EGRID, 2), 512, P_SMEM>>>(xin, p_ws + (size_t)l*RR*256*XROW,
                                                    snd, rcv, rlt);
            k_dense<<<dim3(MTILES, 2), 512, P_SMEM>>>(
                xin, p_sws + (size_t)l*256*XROW, N_ENT, 1, DIM,
                nullptr, 0, p_agg, p_dinv, bias + (size_t)l*DIM, xout[l]);
            xin = xout[l];
        }
        k_dense<<<dim3(MTILES, 5), 512, P_SMEM>>>(
            p_xs2, p_gws, N_ENT, 0, D3, p_xW, D3, nullptr, nullptr, nullptr, nullptr);
        k_dense<<<dim3(MTILES, 5), 512, P_SMEM>>>(
            p_hs, p_gus, N_ENT, 0, D3, p_hU, D3, nullptr, nullptr, nullptr, nullptr);
        k_gru<<<(N_ENT*DIM + 255)/256, 256>>>(b_gates);
    }

    k_score<<<NQ/32, 256>>>(triples, rel_emb, fc1, fc1_b, fc2, fc2_b, out);
}

// round 11
// speedup vs baseline: 3.8171x; 1.4134x over previous
#include <cuda_runtime.h>
#include <cuda_fp16.h>
#include <math.h>
#include <stdint.h>

#define N_ENT 20000
#define DIM   200
#define RR    20
#define NB    20
#define NL    2
#define NT    2
#define NE    250000
#define NQ    8192
#define HID   256
#define D3    600

#define BM 128
#define EGRID 1973
#define EPADTOT (EGRID*BM)
#define MTILES 157
#define GNPAD 640
#define XROW 256              // halves per row (hi only, fp16 scaled)
#define NSLAB 7               // 7*32 = 224 >= 200

#define XS 64.0f
#define WS 2048.0f
#define SCALE_INV (1.0f/131072.0f)

// dynamic smem (bytes): A[3 stages][128 rows][80], B[3 stages][128][80], idx
#define A_STG 10240
#define OFF_B 30720
#define B_STG 10240
#define OFF_SRC 61440
#define OFF_RCV 61952
#define P_SMEM 62464

// ---------------- device scratch ----------------
__device__ __align__(16) float g_relw[NL*RR*DIM*DIM];
__device__ __align__(16) float g_h  [N_ENT*DIM];
__device__ __align__(16) float g_agg[N_ENT*DIM];
__device__ __align__(16) float g_xW [N_ENT*D3];
__device__ __align__(16) float g_hU [N_ENT*D3];
__device__ float g_deg[N_ENT];
__device__ float g_deginv[N_ENT];
__device__ int   g_perm[EPADTOT];
__device__ int   g_cnt[RR];
__device__ int   g_cur[RR];
__device__ __align__(16) __half g_hs [(size_t)N_ENT*XROW];
__device__ __align__(16) __half g_xs1[(size_t)N_ENT*XROW];
__device__ __align__(16) __half g_xs2[(size_t)N_ENT*XROW];
__device__ __align__(16) __half g_ws [(size_t)NL*RR*256*XROW];
__device__ __align__(16) __half g_sws[(size_t)NL*256*XROW];
__device__ __align__(16) __half g_gws[(size_t)GNPAD*XROW];
__device__ __align__(16) __half g_gus[(size_t)GNPAD*XROW];

// ---------------- helpers ----------------
__device__ __forceinline__ uint32_t smem_u32(const void* p) {
    uint32_t a;
    asm("{ .reg .u64 t; cvta.to.shared.u64 t, %1; cvt.u32.u64 %0, t; }" : "=r"(a) : "l"(p));
    return a;
}
__device__ __forceinline__ void mma16(float* c, const uint32_t* a, uint32_t b0, uint32_t b1) {
    asm volatile(
        "mma.sync.aligned.m16n8k16.row.col.f32.f16.f16.f32 "
        "{%0,%1,%2,%3}, {%4,%5,%6,%7}, {%8,%9}, {%0,%1,%2,%3};"
        : "+f"(c[0]), "+f"(c[1]), "+f"(c[2]), "+f"(c[3])
        : "r"(a[0]), "r"(a[1]), "r"(a[2]), "r"(a[3]), "r"(b0), "r"(b1));
}
__device__ __forceinline__ void ldx4(uint32_t* r, uint32_t addr) {
    asm volatile("ldmatrix.sync.aligned.m8n8.x4.shared.b16 {%0,%1,%2,%3}, [%4];"
        : "=r"(r[0]), "=r"(r[1]), "=r"(r[2]), "=r"(r[3]) : "r"(addr));
}
__device__ __forceinline__ void cpa16(uint32_t dst, const void* src) {
    asm volatile("cp.async.cg.shared.global [%0], [%1], 16;" :: "r"(dst), "l"(src) : "memory");
}
__device__ __forceinline__ void cpa_commit() {
    asm volatile("cp.async.commit_group;" ::: "memory");
}
__device__ __forceinline__ void cpa_wait1() {
    asm volatile("cp.async.wait_group 1;" ::: "memory");
}
__device__ __forceinline__ void cpa_wait0() {
    asm volatile("cp.async.wait_group 0;" ::: "memory");
}
__device__ __forceinline__ void red4(float* p, float a, float b, float c, float d) {
    asm volatile("red.global.add.v4.f32 [%0], {%1,%2,%3,%4};"
                 :: "l"(p), "f"(a), "f"(b), "f"(c), "f"(d) : "memory");
}
__device__ __forceinline__ float sigf(float x) { return 1.f / (1.f + expf(-x)); }

// one k32 slab of single-pass fp16 mma on stage st (C = Ah*Bh)
__device__ __forceinline__ void slab_mma(uint32_t sb, int st, int wm, int wn, int lane,
                                         int nlim, float (*acc)[4][4]) {
    if (wn >= nlim) return;   // warp-uniform: whole warp-tile dead
    uint32_t abase = sb + st*A_STG;
    uint32_t bbase = sb + OFF_B + st*B_STG;
    int rowoff = (lane & 15)*80 + ((lane >> 4)*16);
#pragma unroll
    for (int kk = 0; kk < 2; ++kk) {
        uint32_t aH[2][4], bH[2][4];
#pragma unroll
        for (int mi = 0; mi < 2; ++mi)
            ldx4(aH[mi], abase + (wm + mi*16)*80 + rowoff + kk*32);
#pragma unroll
        for (int nj2 = 0; nj2 < 2; ++nj2) {
            if (wn + nj2*16 < nlim)
                ldx4(bH[nj2], bbase + (wn + nj2*16)*80 + rowoff + kk*32);
        }
        // x4 on 16(n)x16(k): reg0=(n0-7,k0-7) reg1=(n8-15,k0-7) reg2=(n0-7,k8-15) reg3=(n8-15,k8-15)
#pragma unroll
        for (int mi = 0; mi < 2; ++mi)
#pragma unroll
            for (int nj = 0; nj < 4; ++nj) {
                if (wn + nj*8 >= nlim) continue;
                mma16(acc[mi][nj], aH[mi], bH[nj>>1][nj&1], bH[nj>>1][(nj&1)+2]);
            }
    }
}

// ---------------- small utility kernels ----------------
__global__ void k_zerof(float* p, int n) {
    int i = blockIdx.x*blockDim.x + threadIdx.x;
    for (; i < n; i += gridDim.x*blockDim.x) p[i] = 0.f;
}
__global__ void k_copy(float* dst, const float* src, int n) {
    int i = blockIdx.x*blockDim.x + threadIdx.x;
    for (; i < n; i += gridDim.x*blockDim.x) dst[i] = src[i];
}
// fused per-timestep setup: perm=-1, deg=0, cnt=0
__global__ void k_setup() {
    int i = blockIdx.x*blockDim.x + threadIdx.x;
    int stride = gridDim.x*blockDim.x;
    for (int j = i; j < EPADTOT; j += stride) g_perm[j] = -1;
    for (int j = i; j < N_ENT; j += stride) g_deg[j] = 0.f;
    if (i < RR) g_cnt[i] = 0;
}

__global__ void k_relw(const float* __restrict__ basis, const float* __restrict__ coeff) {
    __shared__ float s_co[NL*RR*NB];
    int tid = threadIdx.x;
    for (int i = tid; i < NL*RR*NB; i += blockDim.x) s_co[i] = coeff[i];
    __syncthreads();
    int gid = blockIdx.x*blockDim.x + tid;
    if (gid >= NL*DIM*DIM) return;
    int l = gid / (DIM*DIM);
    int rem = gid % (DIM*DIM);
    int i = rem / DIM, o = rem % DIM;
    float acc[RR];
#pragma unroll
    for (int r = 0; r < RR; ++r) acc[r] = 0.f;
    for (int b = 0; b < NB; ++b) {
        float bv = basis[((l*NB + b)*DIM + i)*DIM + o];
#pragma unroll
        for (int r = 0; r < RR; ++r) acc[r] += s_co[(l*RR + r)*NB + b] * bv;
    }
    for (int r = 0; r < RR; ++r)
        g_relw[((l*RR + r)*DIM + i)*DIM + o] = acc[r];
}

// transpose + scaled fp16: dst[b][n][k] = fp16(WS * src[b][k][n])
__global__ void k_splitw(const float* __restrict__ src, __half* __restrict__ dst,
                         int Nsrc, int Nvalid, size_t sstride, size_t dstride) {
    int b = blockIdx.z;
    int idx = blockIdx.x*blockDim.x + threadIdx.x;
    int n = idx >> 8, k = idx & 255;
    float v = 0.f;
    if (n < Nvalid && k < DIM) v = src[b*sstride + (size_t)k*Nsrc + n] * WS;
    dst[b*dstride + (size_t)n*XROW + k] = __float2half_rn(v);
}

__global__ void k_splitx(const float* __restrict__ src, __half* __restrict__ dst) {
    int idx = blockIdx.x*blockDim.x + threadIdx.x;
    if (idx >= N_ENT*256) return;
    int n = idx >> 8, c = idx & 255;
    float v = (c < DIM) ? src[(size_t)n*DIM + c] * XS : 0.f;
    dst[(size_t)n*XROW + c] = __float2half_rn(v);
}

__global__ void k_deg_acc(const int* __restrict__ rcv) {
    int i = blockIdx.x*blockDim.x + threadIdx.x;
    for (; i < NE; i += gridDim.x*blockDim.x) atomicAdd(&g_deg[rcv[i]], 1.f);
}
__global__ void k_deginv() {
    int i = blockIdx.x*blockDim.x + threadIdx.x;
    if (i < N_ENT) g_deginv[i] = 1.f / fmaxf(g_deg[i], 1.f);
}
__global__ void k_hist(const int* __restrict__ rel) {
    __shared__ int s_cnt[RR];
    int tid = threadIdx.x;
    if (tid < RR) s_cnt[tid] = 0;
    __syncthreads();
    int i = blockIdx.x*blockDim.x + tid;
    for (; i < NE; i += gridDim.x*blockDim.x) atomicAdd(&s_cnt[rel[i]], 1);
    __syncthreads();
    if (tid < RR) atomicAdd(&g_cnt[tid], s_cnt[tid]);
}
__global__ void k_scan() {
    int run = 0;
    for (int r = 0; r < RR; ++r) {
        g_cur[r] = run;
        run += ((g_cnt[r] + BM - 1) / BM) * BM;
    }
}
__global__ void k_scatter(const int* __restrict__ rel) {
    int i = blockIdx.x*blockDim.x + threadIdx.x;
    for (; i < NE; i += gridDim.x*blockDim.x) {
        int r = rel[i];
        int p = atomicAdd(&g_cur[r], 1);
        g_perm[p] = i;
    }
}

// ---------------- edge gather-GEMM-scatter ----------------
__global__ void __launch_bounds__(512, 2)
k_edge(const __half* __restrict__ xs, const __half* __restrict__ wsl,
       const int* __restrict__ snd, const int* __restrict__ rcv,
       const int* __restrict__ relt) {
    extern __shared__ __align__(16) char sm[];
    uint32_t sb = smem_u32(sm);
    int* s_src = (int*)(sm + OFF_SRC);
    int* s_rcv = (int*)(sm + OFF_RCV);
    int tid = threadIdx.x, lane = tid & 31, w = tid >> 5;

    int e0 = g_perm[blockIdx.x*BM];
    if (e0 < 0) return;
    int rel = relt[e0];
    if (tid < BM) {
        int e = g_perm[blockIdx.x*BM + tid];
        int sv = 0, rv = -1;
        if (e >= 0) { sv = snd[e]; rv = rcv[e]; }
        s_src[tid] = sv; s_rcv[tid] = rv;
    }
    __syncthreads();

    const __half* wr = wsl + (size_t)rel * (256*XROW);
    int n0 = blockIdx.y * BM;
    int nlim = DIM - n0; if (nlim > BM) nlim = BM;
    int wm = (w & 3)*32, wn = (w >> 2)*32;
    int grp = lane >> 2, qid = lane & 3;

    float acc[2][4][4];
#pragma unroll
    for (int a = 0; a < 2; ++a)
#pragma unroll
        for (int b = 0; b < 4; ++b)
#pragma unroll
            for (int c = 0; c < 4; ++c) acc[a][b][c] = 0.f;

#define E_ISSUE(s, st)                                                           \
    {                                                                            \
        for (int j = tid; j < 1024; j += 512) {                                  \
            int row = (j >> 2) & 127, ch = j & 3;                                \
            if (j < 512) {                                                       \
                cpa16(sb + (st)*A_STG + row*80 + ch*16,                          \
                      xs + (size_t)s_src[row]*XROW + (s)*32 + ch*8);             \
            } else {                                                             \
                cpa16(sb + OFF_B + (st)*B_STG + row*80 + ch*16,                  \
                      wr + (size_t)(n0 + row)*XROW + (s)*32 + ch*8);             \
            }                                                                    \
        }                                                                        \
        cpa_commit();                                                            \
    }

    E_ISSUE(0, 0);
    E_ISSUE(1, 1);
#pragma unroll
    for (int s = 0; s < NSLAB; ++s) {
        if (s + 1 < NSLAB) cpa_wait1(); else cpa_wait0();
        __syncthreads();                        // single barrier per slab
        if (s + 2 < NSLAB) E_ISSUE(s + 2, (s + 2) % 3);
        slab_mma(sb, s % 3, wm, wn, lane, nlim, acc);
    }
#undef E_ISSUE

    // scatter epilogue: butterfly-shuffle to 4-consecutive cols, then red.v4
#pragma unroll
    for (int mi = 0; mi < 2; ++mi) {
        int r_e = wm + mi*16 + grp;
        int rv_e = s_rcv[r_e], rv_o = s_rcv[r_e + 8];
#pragma unroll
        for (int nj = 0; nj < 4; ++nj) {
            if (wn + nj*8 >= nlim) continue;
            float* c = acc[mi][nj];
            float e0f = __shfl_xor_sync(0xffffffffu, c[0], 1);
            float e1f = __shfl_xor_sync(0xffffffffu, c[1], 1);
            float e2f = __shfl_xor_sync(0xffffffffu, c[2], 1);
            float e3f = __shfl_xor_sync(0xffffffffu, c[3], 1);
            int colb = n0 + wn + nj*8 + (qid & ~1)*2;
            if ((qid & 1) == 0) {
                if (rv_e >= 0)
                    red4(g_agg + (size_t)rv_e*DIM + colb,
                         c[0]*SCALE_INV, c[1]*SCALE_INV, e0f*SCALE_INV, e1f*SCALE_INV);
            } else {
                if (rv_o >= 0)
                    red4(g_agg + (size_t)rv_o*DIM + colb,
                         e2f*SCALE_INV, e3f*SCALE_INV, c[2]*SCALE_INV, c[3]*SCALE_INV);
            }
        }
    }
}

// ---------------- dense GEMM ----------------
__global__ void __launch_bounds__(512, 2)
k_dense(const __half* __restrict__ Axs, const __half* __restrict__ Bws,
        int M, int mode, int Nvalid,
        float* __restrict__ C, int ldC,
        const float* __restrict__ agg, const float* __restrict__ dinv,
        const float* __restrict__ bias, __half* __restrict__ out_xs) {
    extern __shared__ __align__(16) char sm[];
    uint32_t sb = smem_u32(sm);
    int tid = threadIdx.x, lane = tid & 31, w = tid >> 5;
    int m0 = blockIdx.x * BM;
    int n0 = blockIdx.y * BM;
    int nlim = Nvalid - n0; if (nlim > BM) nlim = BM; if (nlim < 0) nlim = 0;
    int wm = (w & 3)*32, wn = (w >> 2)*32;
    int grp = lane >> 2, qid = lane & 3;

    float acc[2][4][4];
#pragma unroll
    for (int a = 0; a < 2; ++a)
#pragma unroll
        for (int b = 0; b < 4; ++b)
#pragma unroll
            for (int c = 0; c < 4; ++c) acc[a][b][c] = 0.f;

#define D_ISSUE(s, st)                                                           \
    {                                                                            \
        for (int j = tid; j < 1024; j += 512) {                                  \
            int row = (j >> 2) & 127, ch = j & 3;                                \
            if (j < 512) {                                                       \
                int gm = m0 + row; if (gm >= M) gm = 0;                          \
                cpa16(sb + (st)*A_STG + row*80 + ch*16,                          \
                      Axs + (size_t)gm*XROW + (s)*32 + ch*8);                    \
            } else {                                                             \
                cpa16(sb + OFF_B + (st)*B_STG + row*80 + ch*16,                  \
                      Bws + (size_t)(n0 + row)*XROW + (s)*32 + ch*8);            \
            }                                                                    \
        }                                                                        \
        cpa_commit();                                                            \
    }

    D_ISSUE(0, 0);
    D_ISSUE(1, 1);
#pragma unroll
    for (int s = 0; s < NSLAB; ++s) {
        if (s + 1 < NSLAB) cpa_wait1(); else cpa_wait0();
        __syncthreads();
        if (s + 2 < NSLAB) D_ISSUE(s + 2, (s + 2) % 3);
        slab_mma(sb, s % 3, wm, wn, lane, nlim, acc);
    }
#undef D_ISSUE

#pragma unroll
    for (int mi = 0; mi < 2; ++mi) {
        int r0 = m0 + wm + mi*16 + grp;
        int r1 = r0 + 8;
#pragma unroll
        for (int nj = 0; nj < 4; ++nj) {
            if (wn + nj*8 >= nlim) continue;   // dead n-block: pad stays zero-init
            int col = n0 + wn + nj*8 + qid*2;
            float* c = acc[mi][nj];
            if (mode == 0) {
                if (col >= Nvalid) continue;
                if (r0 < M) *(float2*)(C + (size_t)r0*ldC + col) =
                    make_float2(c[0]*SCALE_INV, c[1]*SCALE_INV);
                if (r1 < M) *(float2*)(C + (size_t)r1*ldC + col) =
                    make_float2(c[2]*SCALE_INV, c[3]*SCALE_INV);
            } else {
#pragma unroll
                for (int h = 0; h < 2; ++h) {
                    int row = h ? r1 : r0;
                    if (row >= M) continue;
                    float v0 = 0.f, v1 = 0.f;
                    if (col < DIM) {
                        float dv = dinv[row];
                        float a0 = agg[(size_t)row*DIM + col]*dv + bias[col];
                        float a1 = agg[(size_t)row*DIM + col + 1]*dv + bias[col + 1];
                        v0 = fmaxf(c[h*2+0]*SCALE_INV + a0, 0.f) * XS;
                        v1 = fmaxf(c[h*2+1]*SCALE_INV + a1, 0.f) * XS;
                    }
                    *(__half2*)(out_xs + (size_t)row*XROW + col) =
                        __halves2half2(__float2half_rn(v0), __float2half_rn(v1));
                }
            }
        }
    }
}

__global__ void k_gru(const float* __restrict__ bg) {
    int idx = blockIdx.x*blockDim.x + threadIdx.x;
    if (idx >= N_ENT*DIM) return;
    int n = idx / DIM, c = idx % DIM;
    size_t b = (size_t)n*D3;
    float r  = sigf(g_xW[b + c]        + g_hU[b + c]        + bg[c]);
    float z  = sigf(g_xW[b + DIM + c]  + g_hU[b + DIM + c]  + bg[DIM + c]);
    float hu3 = g_hU[b + 2*DIM + c];
    float ht = tanhf(g_xW[b + 2*DIM + c] + hu3 + bg[2*DIM + c] + r * hu3);
    float h0 = g_h[idx];
    float hn = (1.f - z)*h0 + z*ht;
    g_h[idx] = hn;
    g_hs[(size_t)n*XROW + c] = __float2half_rn(hn * XS);
}

__global__ void __launch_bounds__(256)
k_score(const int* __restrict__ triples, const float* __restrict__ rel_emb,
        const float* __restrict__ fc1, const float* __restrict__ b1,
        const float* __restrict__ fc2, const float* __restrict__ fc2b,
        float* __restrict__ out) {
    __shared__ float As[32][8];
    __shared__ float Bs[8][HID];
    __shared__ int s_s[32], s_r[32], s_o[32];
    int tid = threadIdx.x;
    int qbase = blockIdx.x * 32;
    if (tid < 32) {
        s_s[tid] = triples[(qbase + tid)*3 + 0];
        s_r[tid] = triples[(qbase + tid)*3 + 1];
        s_o[tid] = triples[(qbase + tid)*3 + 2];
    }
    __syncthreads();
    int w = tid >> 5, lane = tid & 31;
    float acc[4][8];
#pragma unroll
    for (int i = 0; i < 4; ++i)
#pragma unroll
        for (int j = 0; j < 8; ++j) acc[i][j] = 0.f;

    for (int k0 = 0; k0 < D3; k0 += 8) {
        {
            int qi = tid >> 3, kk = tid & 7, k = k0 + kk;
            float v;
            if (k < DIM)            v = g_h[(size_t)s_s[qi]*DIM + k];
            else if (k < 2*DIM)     v = rel_emb[(size_t)s_r[qi]*DIM + (k - DIM)];
            else                    v = g_h[(size_t)s_o[qi]*DIM + (k - 2*DIM)];
            As[qi][kk] = v;
        }
        {
            int kr = tid >> 5, cb = tid & 31;
#pragma unroll
            for (int j = 0; j < 8; ++j)
                Bs[kr][cb + 32*j] = fc1[(size_t)(k0 + kr)*HID + cb + 32*j];
        }
        __syncthreads();
#pragma unroll
        for (int kk = 0; kk < 8; ++kk) {
#pragma unroll
            for (int i = 0; i < 4; ++i) {
                float a = As[w*4 + i][kk];
#pragma unroll
                for (int j = 0; j < 8; ++j)
                    acc[i][j] += a * Bs[kk][lane + 32*j];
            }
        }
        __syncthreads();
    }
#pragma unroll
    for (int i = 0; i < 4; ++i) {
        float p = 0.f;
#pragma unroll
        for (int j = 0; j < 8; ++j) {
            int col = lane + 32*j;
            float hv = fmaxf(acc[i][j] + b1[col], 0.f);
            p += hv * fc2[col];
        }
#pragma unroll
        for (int off = 16; off > 0; off >>= 1)
            p += __shfl_down_sync(0xffffffffu, p, off);
        if (lane == 0) out[qbase + w*4 + i] = p + fc2b[0];
    }
}

// ---------------- host ----------------
extern "C" void kernel_launch(void* const* d_in, const int* in_sizes, int n_in,
                              void* d_out, int out_size) {
    const float* entity_emb = (const float*)d_in[0];
    const float* basis      = (const float*)d_in[1];
    const float* coeff      = (const float*)d_in[2];
    const float* self_w     = (const float*)d_in[3];
    const float* bias       = (const float*)d_in[4];
    const float* W_gates    = (const float*)d_in[5];
    const float* U_gates    = (const float*)d_in[6];
    const float* b_gates    = (const float*)d_in[7];
    const float* rel_emb    = (const float*)d_in[8];
    const float* fc1        = (const float*)d_in[9];
    const float* fc1_b      = (const float*)d_in[10];
    const float* fc2        = (const float*)d_in[11];
    const float* fc2_b      = (const float*)d_in[12];
    const int*   senders    = (const int*)d_in[13];
    const int*   receivers  = (const int*)d_in[14];
    const int*   rel_types  = (const int*)d_in[15];
    const int*   triples    = (const int*)d_in[16];
    float* out = (float*)d_out;

    cudaFuncSetAttribute(k_edge,  cudaFuncAttributeMaxDynamicSharedMemorySize, P_SMEM);
    cudaFuncSetAttribute(k_dense, cudaFuncAttributeMaxDynamicSharedMemorySize, P_SMEM);

    float *p_relw, *p_h, *p_agg, *p_dinv, *p_xW, *p_hU;
    __half *p_hs, *p_xs1, *p_xs2, *p_ws, *p_sws, *p_gws, *p_gus;
    cudaGetSymbolAddress((void**)&p_relw, g_relw);
    cudaGetSymbolAddress((void**)&p_h,    g_h);
    cudaGetSymbolAddress((void**)&p_agg,  g_agg);
    cudaGetSymbolAddress((void**)&p_dinv, g_deginv);
    cudaGetSymbolAddress((void**)&p_xW,   g_xW);
    cudaGetSymbolAddress((void**)&p_hU,   g_hU);
    cudaGetSymbolAddress((void**)&p_hs,   g_hs);
    cudaGetSymbolAddress((void**)&p_xs1,  g_xs1);
    cudaGetSymbolAddress((void**)&p_xs2,  g_xs2);
    cudaGetSymbolAddress((void**)&p_ws,   g_ws);
    cudaGetSymbolAddress((void**)&p_sws,  g_sws);
    cudaGetSymbolAddress((void**)&p_gws,  g_gws);
    cudaGetSymbolAddress((void**)&p_gus,  g_gus);

    k_relw<<<(NL*DIM*DIM + 255)/256, 256>>>(basis, coeff);
    k_splitw<<<dim3(256, 1, NL*RR), 256>>>(p_relw, p_ws, DIM, DIM,
                                           (size_t)DIM*DIM, (size_t)256*XROW);
    k_splitw<<<dim3(256, 1, NL), 256>>>(self_w, p_sws, DIM, DIM,
                                        (size_t)DIM*DIM, (size_t)256*XROW);
    k_splitw<<<dim3(GNPAD, 1, 1), 256>>>(W_gates, p_gws, D3, D3, 0, 0);
    k_splitw<<<dim3(GNPAD, 1, 1), 256>>>(U_gates, p_gus, D3, D3, 0, 0);
    k_splitx<<<(N_ENT*256 + 255)/256, 256>>>(entity_emb, p_hs);
    k_copy<<<1024, 256>>>(p_h, entity_emb, N_ENT*DIM);

    for (int t = 0; t < NT; ++t) {
        const int* snd = senders   + (size_t)t*NE;
        const int* rcv = receivers + (size_t)t*NE;
        const int* rlt = rel_types + (size_t)t*NE;

        k_setup<<<512, 256>>>();
        k_deg_acc<<<512, 256>>>(rcv);
        k_deginv<<<(N_ENT + 255)/256, 256>>>();
        k_hist<<<256, 256>>>(rlt);
        k_scan<<<1, 1>>>();
        k_scatter<<<512, 256>>>(rlt);

        const __half* xin = p_hs;
        __half* xout[2] = { p_xs1, p_xs2 };
        for (int l = 0; l < NL; ++l) {
            k_zerof<<<1024, 256>>>(p_agg, N_ENT*DIM);
            k_edge<<<dim3(EGRID, 2), 512, P_SMEM>>>(xin, p_ws + (size_t)l*RR*256*XROW,
                                                    snd, rcv, rlt);
            k_dense<<<dim3(MTILES, 2), 512, P_SMEM>>>(
                xin, p_sws + (size_t)l*256*XROW, N_ENT, 1, DIM,
                nullptr, 0, p_agg, p_dinv, bias + (size_t)l*DIM, xout[l]);
            xin = xout[l];
        }
        k_dense<<<dim3(MTILES, 5), 512, P_SMEM>>>(
            p_xs2, p_gws, N_ENT, 0, D3, p_xW, D3, nullptr, nullptr, nullptr, nullptr);
        k_dense<<<dim3(MTILES, 5), 512, P_SMEM>>>(
            p_hs, p_gus, N_ENT, 0, D3, p_hU, D3, nullptr, nullptr, nullptr, nullptr);
        k_gru<<<(N_ENT*DIM + 255)/256, 256>>>(b_gates);
    }

    k_score<<<NQ/32, 256>>>(triples, rel_emb, fc1, fc1_b, fc2, fc2_b, out);
}